// round 11
// baseline (speedup 1.0000x reference)
#include <cuda_runtime.h>
#include <cuda_bf16.h>
#include <cuda_fp16.h>

// ---------------- problem constants ----------------
constexpr int N_CHR = 50000, E_CHR = 500000;
constexpr int N_SLV = 30000, E_SLV = 300000;
constexpr int NTOT = N_CHR + N_SLV;      // 80000
constexpr int ETOT = E_CHR + E_SLV;      // 800000
constexpr int B    = 256;
constexpr int FEAT = 64;
constexpr int DIM  = 128;
constexpr int HALF = 64;
constexpr int ENS  = 3;
constexpr int SCAN_BLK = 1024;
constexpr int NB_SCAN = (NTOT + SCAN_BLK - 1) / SCAN_BLK;  // 79

// ---------------- scratch (device globals; no allocations allowed) --------
__device__ __align__(128) __half g_aggx[(size_t)NTOT * FEAT];
__device__ __align__(128) __half g_buf1[(size_t)NTOT * ENS * DIM];   // t2
__device__ __align__(128) __half g_buf2[(size_t)NTOT * ENS * DIM];   // t1
__device__ float g_pool[(size_t)B * 2 * ENS * HALF];
__device__ int   g_deg[NTOT];        // ZERO at entry of every run (static init + re-zero in gather64)
__device__ int   g_incl[NTOT];
__device__ int   g_off[NTOT];
__device__ int   g_cursor[NTOT];     // after fill: end offset of each node
__device__ int   g_csr[ETOT];
__device__ int   g_bsumx[128];

// ---------------- helpers ----------------
__device__ __forceinline__ void red_add_v4(float* p, float4 v) {
    asm volatile("red.global.add.v4.f32 [%0], {%1,%2,%3,%4};"
                 :: "l"(p), "f"(v.x), "f"(v.y), "f"(v.z), "f"(v.w)
                 : "memory");
}

__device__ __forceinline__ void edge_sd(int e, const int* __restrict__ ec,
                                        const int* __restrict__ es, int& src, int& dst) {
    if (e < E_CHR) { src = ec[e]; dst = ec[E_CHR + e]; }
    else { int e2 = e - E_CHR; src = N_CHR + es[e2]; dst = N_CHR + es[E_SLV + e2]; }
}

__device__ __forceinline__ void ldsm_x4(unsigned* r, unsigned addr) {
    asm volatile("ldmatrix.sync.aligned.m8n8.x4.shared.b16 {%0,%1,%2,%3}, [%4];"
                 : "=r"(r[0]), "=r"(r[1]), "=r"(r[2]), "=r"(r[3]) : "r"(addr));
}
__device__ __forceinline__ void ldsm_x2t(unsigned* r, unsigned addr) {
    asm volatile("ldmatrix.sync.aligned.m8n8.x2.trans.shared.b16 {%0,%1}, [%2];"
                 : "=r"(r[0]), "=r"(r[1]) : "r"(addr));
}
__device__ __forceinline__ void mma16816(float* d, const unsigned* a, const unsigned* b) {
    asm volatile("mma.sync.aligned.m16n8k16.row.col.f32.f16.f16.f32 "
                 "{%0,%1,%2,%3}, {%4,%5,%6,%7}, {%8,%9}, {%0,%1,%2,%3};"
                 : "+f"(d[0]), "+f"(d[1]), "+f"(d[2]), "+f"(d[3])
                 : "r"(a[0]), "r"(a[1]), "r"(a[2]), "r"(a[3]), "r"(b[0]), "r"(b[1]));
}
__device__ __forceinline__ void cp_async16z(unsigned sa, const void* g, bool v) {
    int sz = v ? 16 : 0;
    asm volatile("cp.async.cg.shared.global [%0], [%1], 16, %2;"
                 :: "r"(sa), "l"(g), "r"(sz) : "memory");
}
__device__ __forceinline__ void cp_commit() {
    asm volatile("cp.async.commit_group;" ::: "memory");
}
__device__ __forceinline__ void cp_wait1() {
    asm volatile("cp.async.wait_group 1;" ::: "memory");
}
__device__ __forceinline__ unsigned pack2(float x, float y) {
    __half2 h = __floats2half2_rn(x, y);
    return *(unsigned*)&h;
}
__device__ __forceinline__ unsigned pack2r(float x, float y) {
    return pack2(fmaxf(x, 0.f), fmaxf(y, 0.f));
}
__device__ __forceinline__ void acc4(float* a, uint2 v) {
    float2 f0 = __half22float2(*(__half2*)&v.x);
    float2 f1 = __half22float2(*(__half2*)&v.y);
    a[0] += f0.x; a[1] += f0.y; a[2] += f1.x; a[3] += f1.y;
}
__device__ __forceinline__ void acc8(float* a, uint4 v) {
    acc4(a, make_uint2(v.x, v.y));
    acc4(a + 4, make_uint2(v.z, v.w));
}

// ---------------- CSR build ----------------
__global__ void count_deg_kernel(const int* __restrict__ ec, const int* __restrict__ es) {
    int e = blockIdx.x * blockDim.x + threadIdx.x;
    if (e < B * 384 / 4) ((float4*)g_pool)[e] = make_float4(0.f, 0.f, 0.f, 0.f);
    if (e >= ETOT) return;
    int src, dst; edge_sd(e, ec, es, src, dst);
    atomicAdd(&g_deg[dst], 1);
}

__global__ void scan1_kernel(int* __restrict__ bsum_raw) {
    __shared__ int s[SCAN_BLK];
    int tid = threadIdx.x;
    int i = blockIdx.x * SCAN_BLK + tid;
    int v = (i < NTOT) ? g_deg[i] : 0;
    s[tid] = v;
    __syncthreads();
    #pragma unroll
    for (int off = 1; off < SCAN_BLK; off <<= 1) {
        int t = (tid >= off) ? s[tid - off] : 0;
        __syncthreads();
        s[tid] += t;
        __syncthreads();
    }
    if (i < NTOT) g_incl[i] = s[tid];
    if (tid == SCAN_BLK - 1) bsum_raw[blockIdx.x] = s[tid];
}

__global__ void scan2_kernel(const int* __restrict__ bsum_raw) {
    __shared__ int s[128];
    int tid = threadIdx.x;
    int v = (tid < NB_SCAN) ? bsum_raw[tid] : 0;
    s[tid] = v;
    __syncthreads();
    #pragma unroll
    for (int off = 1; off < 128; off <<= 1) {
        int t = (tid >= off) ? s[tid - off] : 0;
        __syncthreads();
        s[tid] += t;
        __syncthreads();
    }
    g_bsumx[tid] = s[tid] - v;  // exclusive
}

__global__ void scan3_kernel() {
    int i = blockIdx.x * blockDim.x + threadIdx.x;
    if (i >= NTOT) return;
    int start = g_incl[i] - g_deg[i] + g_bsumx[i / SCAN_BLK];
    g_off[i] = start;
    g_cursor[i] = start;
}

__global__ void fill_csr_kernel(const int* __restrict__ ec, const int* __restrict__ es) {
    int e = blockIdx.x * blockDim.x + threadIdx.x;
    if (e >= ETOT) return;
    int src, dst; edge_sd(e, ec, es, src, dst);
    int pos = atomicAdd(&g_cursor[dst], 1);
    g_csr[pos] = src;
}

// ---------------- gather64: A x -> fp16 aggx (also re-zeroes g_deg) -------
__global__ __launch_bounds__(256)
void gather64_kernel(const float* __restrict__ xchr, const float* __restrict__ xslv,
                     __half* __restrict__ out) {
    int lane = threadIdx.x & 31;
    int sub = lane >> 4;
    int l = lane & 15;
    unsigned hmask = 0xffffu << (sub * 16);
    int node = ((blockIdx.x * blockDim.x + threadIdx.x) >> 5) * 2 + sub;
    if (node >= NTOT) return;
    int start = g_off[node], deg = g_cursor[node] - start;
    if (l == 0) g_deg[node] = 0;
    float4 a = make_float4(0.f, 0.f, 0.f, 0.f);
    for (int kb = 0; kb < deg; kb += 16) {
        int idx = (kb + l < deg) ? g_csr[start + kb + l] : 0;
        int m = min(16, deg - kb);
        int s = __shfl_sync(hmask, idx, 0, 16);
        const float4* sr = (s < N_CHR) ? (const float4*)(xchr + (size_t)s * 64)
                                       : (const float4*)(xslv + (size_t)(s - N_CHR) * 64);
        float4 p = sr[l];
        for (int k = 0; k < m; k++) {
            float4 c = p;
            if (k + 1 < m) {
                int s2 = __shfl_sync(hmask, idx, k + 1, 16);
                const float4* nr = (s2 < N_CHR) ? (const float4*)(xchr + (size_t)s2 * 64)
                                                : (const float4*)(xslv + (size_t)(s2 - N_CHR) * 64);
                p = nr[l];
            }
            a.x += c.x; a.y += c.y; a.z += c.z; a.w += c.w;
        }
    }
    uint2 u; u.x = pack2(a.x, a.y); u.y = pack2(a.z, a.w);
    *(uint2*)(out + (size_t)node * 64 + l * 4) = u;
}

// ---------------- fused GEMM0+GEMM1: t1 = relu(aggx@W0) @ W1 --------------
// h0 tile lives only in smem. 256 threads, tile = 128 rows.
__global__ __launch_bounds__(256, 1)
void gemm01_kernel(const __half* __restrict__ in, __half* __restrict__ out,
                   const float* __restrict__ W0c, const float* __restrict__ W0s,
                   const float* __restrict__ W1c, const float* __restrict__ W1s) {
    constexpr int TR = 128;
    constexpr int LDA = 72;    // 64 + 8
    constexpr int LDW = 136;   // 128 + 8
    constexpr int ABUF = TR * LDA;

    extern __shared__ __half hsm[];
    __half* sA  = hsm;                         // [2][128][72]
    __half* sW0 = hsm + 2 * ABUF;              // [64][136]
    __half* sW1 = sW0 + 64 * LDW;              // [128][136]
    __half* sH  = sW1 + 128 * LDW;             // [128][136]

    const int e = blockIdx.y;
    const int branch = blockIdx.z;
    const int tid = threadIdx.x;
    const int wid = tid >> 5;
    const int lane = tid & 31;
    const int rowgrp = wid >> 1;   // 4 groups of 32 rows
    const int colgrp = wid & 1;    // 2 groups of 64 cols

    const int base  = branch ? N_CHR : 0;
    const int nrows = branch ? N_SLV : N_CHR;
    const int ntiles = (nrows + TR - 1) / TR;

    // weights fp32 -> fp16 smem [k][n]
    {
        const float* W0 = (branch ? W0s : W0c) + (size_t)e * 64 * 128;
        for (int idx = tid; idx < 64 * 128 / 4; idx += 256) {
            int k = idx / 32, c = idx % 32;
            float4 w = ((const float4*)W0)[idx];
            uint2 u; u.x = pack2(w.x, w.y); u.y = pack2(w.z, w.w);
            *(uint2*)(sW0 + k * LDW + c * 4) = u;
        }
        const float* W1 = (branch ? W1s : W1c) + (size_t)e * 128 * 128;
        for (int idx = tid; idx < 128 * 128 / 4; idx += 256) {
            int k = idx / 32, c = idx % 32;
            float4 w = ((const float4*)W1)[idx];
            uint2 u; u.x = pack2(w.x, w.y); u.y = pack2(w.z, w.w);
            *(uint2*)(sW1 + k * LDW + c * 4) = u;
        }
    }

    unsigned sa_base = (unsigned)__cvta_generic_to_shared(sA);
    unsigned sw0_base = (unsigned)__cvta_generic_to_shared(sW0);
    unsigned sw1_base = (unsigned)__cvta_generic_to_shared(sW1);
    unsigned sh_base = (unsigned)__cvta_generic_to_shared(sH);

    auto load_tile = [&](int t, int buf) {
        int row0 = base + t * TR;
        for (int i = tid; i < TR * 8; i += 256) {   // 8 uint4 per 64-wide row
            int r = i >> 3, c = i & 7;
            bool valid = (row0 + r) < base + nrows;
            int rr = valid ? (row0 + r) : 0;
            const void* g = in + (size_t)rr * 64 + c * 8;
            cp_async16z(sa_base + (unsigned)(buf * ABUF + r * LDA + c * 8) * 2, g, valid);
        }
    };

    int t0 = blockIdx.x;
    if (t0 < ntiles) load_tile(t0, 0);
    cp_commit();

    int bi = 0;
    for (int t = t0; t < ntiles; t += gridDim.x, bi ^= 1) {
        int tn = t + gridDim.x;
        if (tn < ntiles) load_tile(tn, bi ^ 1);
        cp_commit();
        cp_wait1();
        __syncthreads();

        int row0 = base + t * TR;
        int rcnt = min(TR, base + nrows - row0);
        unsigned abuf = sa_base + (unsigned)(bi * ABUF) * 2;
        int lrow = lane >> 2, lcol = (lane & 3) * 2;

        // ---- MMA1: h0 = relu(A @ W0) -> sH ----
        {
            float acc[2][8][4];
            #pragma unroll
            for (int mt = 0; mt < 2; mt++)
                #pragma unroll
                for (int nt = 0; nt < 8; nt++)
                    #pragma unroll
                    for (int q = 0; q < 4; q++) acc[mt][nt][q] = 0.f;
            #pragma unroll
            for (int ks = 0; ks < 4; ks++) {   // K = 64
                unsigned a[2][4];
                #pragma unroll
                for (int mt = 0; mt < 2; mt++) {
                    int r = rowgrp * 32 + mt * 16 + (lane & 15);
                    int c = ks * 16 + (lane >> 4) * 8;
                    ldsm_x4(a[mt], abuf + (unsigned)(r * LDA + c) * 2);
                }
                #pragma unroll
                for (int nt = 0; nt < 8; nt++) {
                    unsigned b[2];
                    int rk = ks * 16 + (lane & 15);
                    int cn = colgrp * 64 + nt * 8;
                    ldsm_x2t(b, sw0_base + (unsigned)(rk * LDW + cn) * 2);
                    #pragma unroll
                    for (int mt = 0; mt < 2; mt++)
                        mma16816(acc[mt][nt], a[mt], b);
                }
            }
            // epilogue 1: relu + fp16 into sH (unconditional; invalid rows are 0)
            #pragma unroll
            for (int mt = 0; mt < 2; mt++) {
                #pragma unroll
                for (int nt = 0; nt < 8; nt++) {
                    int col = colgrp * 64 + nt * 8 + lcol;
                    int r1 = rowgrp * 32 + mt * 16 + lrow;
                    *(__half2*)(sH + r1 * LDW + col) =
                        __floats2half2_rn(fmaxf(acc[mt][nt][0], 0.f), fmaxf(acc[mt][nt][1], 0.f));
                    *(__half2*)(sH + (r1 + 8) * LDW + col) =
                        __floats2half2_rn(fmaxf(acc[mt][nt][2], 0.f), fmaxf(acc[mt][nt][3], 0.f));
                }
            }
        }
        __syncthreads();

        // ---- MMA2: t1 = h0 @ W1 -> gmem ----
        {
            float acc[2][8][4];
            #pragma unroll
            for (int mt = 0; mt < 2; mt++)
                #pragma unroll
                for (int nt = 0; nt < 8; nt++)
                    #pragma unroll
                    for (int q = 0; q < 4; q++) acc[mt][nt][q] = 0.f;
            #pragma unroll
            for (int ks = 0; ks < 8; ks++) {   // K = 128
                unsigned a[2][4];
                #pragma unroll
                for (int mt = 0; mt < 2; mt++) {
                    int r = rowgrp * 32 + mt * 16 + (lane & 15);
                    int c = ks * 16 + (lane >> 4) * 8;
                    ldsm_x4(a[mt], sh_base + (unsigned)(r * LDW + c) * 2);
                }
                #pragma unroll
                for (int nt = 0; nt < 8; nt++) {
                    unsigned b[2];
                    int rk = ks * 16 + (lane & 15);
                    int cn = colgrp * 64 + nt * 8;
                    ldsm_x2t(b, sw1_base + (unsigned)(rk * LDW + cn) * 2);
                    #pragma unroll
                    for (int mt = 0; mt < 2; mt++)
                        mma16816(acc[mt][nt], a[mt], b);
                }
            }
            #pragma unroll
            for (int mt = 0; mt < 2; mt++) {
                #pragma unroll
                for (int nt = 0; nt < 8; nt++) {
                    int col = colgrp * 64 + nt * 8 + lcol;
                    int r1 = rowgrp * 32 + mt * 16 + lrow;
                    if (r1 < rcnt)
                        *(__half2*)(out + (size_t)(row0 + r1) * 384 + e * 128 + col) =
                            __floats2half2_rn(acc[mt][nt][0], acc[mt][nt][1]);
                    if (r1 + 8 < rcnt)
                        *(__half2*)(out + (size_t)(row0 + r1 + 8) * 384 + e * 128 + col) =
                            __floats2half2_rn(acc[mt][nt][2], acc[mt][nt][3]);
                }
            }
        }
        __syncthreads();
    }
}

// ---------------- fused gather + GEMM2: t2 = relu(A t1)|_e @ W2 ------------
// Each block gathers its ensemble's 128-wide slice of t1 for 128 nodes into
// smem (fp32 accumulate -> relu -> fp16), then does the MMA with W2.
__global__ __launch_bounds__(256, 1)
void gather_gemm2_kernel(const __half* __restrict__ in, __half* __restrict__ out,
                         const float* __restrict__ W2c, const float* __restrict__ W2s) {
    constexpr int TR = 128;
    constexpr int LDH = 136;   // 128 + 8
    constexpr int LDB = 72;    // 64 + 8

    extern __shared__ __half hsm[];
    __half* sH = hsm;                 // [128][136] gathered+relu'd agg1 slice
    __half* sB = hsm + TR * LDH;      // [128][72]  W2 fp16

    const int e = blockIdx.y;
    const int branch = blockIdx.z;
    const int tid = threadIdx.x;
    const int wid = tid >> 5;
    const int lane = tid & 31;
    const int sub = lane >> 4;
    const int l = lane & 15;
    const unsigned hmask = 0xffffu << (sub * 16);

    const int base  = branch ? N_CHR : 0;
    const int nrows = branch ? N_SLV : N_CHR;
    const int rend  = base + nrows;
    const int ntiles = (nrows + TR - 1) / TR;

    // W2 fp32 -> fp16 smem [k][n]
    {
        const float* W2 = (branch ? W2s : W2c) + (size_t)e * 128 * 64;
        for (int idx = tid; idx < 128 * 64 / 4; idx += 256) {
            int k = idx / 16, c = idx % 16;
            float4 w = ((const float4*)W2)[idx];
            uint2 u; u.x = pack2(w.x, w.y); u.y = pack2(w.z, w.w);
            *(uint2*)(sB + k * LDB + c * 4) = u;
        }
    }

    unsigned sh_base = (unsigned)__cvta_generic_to_shared(sH);
    unsigned sb_base = (unsigned)__cvta_generic_to_shared(sB);
    const __half* ine = in + e * 128;   // ensemble slice base (stride 384)

    for (int t = blockIdx.x; t < ntiles; t += gridDim.x) {
        int row0 = base + t * TR;
        int rcnt = min(TR, rend - row0);

        // ---- phase 1: gather 16 nodes per warp (half-warp per node) ----
        #pragma unroll 1
        for (int p = 0; p < 8; p++) {
            int nl = wid * 16 + p * 2 + sub;
            int node = row0 + nl;
            float a[8];
            #pragma unroll
            for (int i = 0; i < 8; i++) a[i] = 0.f;
            if (node < rend) {
                int start = g_off[node], deg = g_cursor[node] - start;
                for (int kb = 0; kb < deg; kb += 16) {
                    int idx = (kb + l < deg) ? g_csr[start + kb + l] : 0;
                    int m = min(16, deg - kb);
                    int s = __shfl_sync(hmask, idx, 0, 16);
                    uint4 pv = ((const uint4*)(ine + (size_t)s * 384))[l];
                    for (int k = 0; k < m; k++) {
                        uint4 c = pv;
                        if (k + 1 < m) {
                            int s2 = __shfl_sync(hmask, idx, k + 1, 16);
                            pv = ((const uint4*)(ine + (size_t)s2 * 384))[l];
                        }
                        acc8(a, c);
                    }
                }
            }
            uint4 o;
            o.x = pack2r(a[0], a[1]); o.y = pack2r(a[2], a[3]);
            o.z = pack2r(a[4], a[5]); o.w = pack2r(a[6], a[7]);
            *(uint4*)(sH + nl * LDH + l * 8) = o;
        }
        __syncthreads();

        // ---- phase 2: MMA (128x64, K=128), warp tile 16x64 ----
        float acc[8][4];
        #pragma unroll
        for (int nt = 0; nt < 8; nt++)
            #pragma unroll
            for (int q = 0; q < 4; q++) acc[nt][q] = 0.f;
        #pragma unroll
        for (int ks = 0; ks < 8; ks++) {
            unsigned a[4];
            int r = wid * 16 + (lane & 15);
            int c = ks * 16 + (lane >> 4) * 8;
            ldsm_x4(a, sh_base + (unsigned)(r * LDH + c) * 2);
            #pragma unroll
            for (int nt = 0; nt < 8; nt++) {
                unsigned b[2];
                int rk = ks * 16 + (lane & 15);
                ldsm_x2t(b, sb_base + (unsigned)(rk * LDB + nt * 8) * 2);
                mma16816(acc[nt], a, b);
            }
        }
        int lrow = lane >> 2, lcol = (lane & 3) * 2;
        #pragma unroll
        for (int nt = 0; nt < 8; nt++) {
            int col = nt * 8 + lcol;
            int r1 = wid * 16 + lrow;
            if (r1 < rcnt)
                *(__half2*)(out + (size_t)(row0 + r1) * 192 + e * 64 + col) =
                    __floats2half2_rn(acc[nt][0], acc[nt][1]);
            if (r1 + 8 < rcnt)
                *(__half2*)(out + (size_t)(row0 + r1 + 8) * 192 + e * 64 + col) =
                    __floats2half2_rn(acc[nt][2], acc[nt][3]);
        }
        __syncthreads();
    }
}

// ---------------- layer-2 aggregation + relu + global_add_pool -------------
__global__ __launch_bounds__(256)
void gather192h_pool_kernel(const __half* __restrict__ in,
                            const int* __restrict__ bchr, const int* __restrict__ bslv) {
    int lane = threadIdx.x & 31;
    int sub = lane >> 4;
    int l = lane & 15;
    unsigned hmask = 0xffffu << (sub * 16);
    int node = ((blockIdx.x * blockDim.x + threadIdx.x) >> 5) * 2 + sub;
    if (node >= NTOT) return;
    int start = g_off[node], deg = g_cursor[node] - start;
    float a[12];
    #pragma unroll
    for (int i = 0; i < 12; i++) a[i] = 0.f;
    for (int kb = 0; kb < deg; kb += 16) {
        int idx = (kb + l < deg) ? g_csr[start + kb + l] : 0;
        int m = min(16, deg - kb);
        int s = __shfl_sync(hmask, idx, 0, 16);
        const uint2* sr = (const uint2*)(in + (size_t)s * 192);
        uint2 p0 = sr[l], p1 = sr[l + 16], p2 = sr[l + 32];
        for (int k = 0; k < m; k++) {
            uint2 c0 = p0, c1 = p1, c2 = p2;
            if (k + 1 < m) {
                int s2 = __shfl_sync(hmask, idx, k + 1, 16);
                const uint2* nr = (const uint2*)(in + (size_t)s2 * 192);
                p0 = nr[l]; p1 = nr[l + 16]; p2 = nr[l + 32];
            }
            acc4(a, c0); acc4(a + 4, c1); acc4(a + 8, c2);
        }
    }
    #pragma unroll
    for (int i = 0; i < 12; i++) a[i] = fmaxf(a[i], 0.f);
    int b, colbase;
    if (node < N_CHR) { b = bchr[node]; colbase = 0; }
    else              { b = bslv[node - N_CHR]; colbase = 192; }
    float* prow = g_pool + (size_t)b * 384 + colbase;
    red_add_v4(prow + l * 4,       make_float4(a[0], a[1], a[2], a[3]));
    red_add_v4(prow + 64 + l * 4,  make_float4(a[4], a[5], a[6], a[7]));
    red_add_v4(prow + 128 + l * 4, make_float4(a[8], a[9], a[10], a[11]));
}

// ---------------- head: projection heads + concat + fc1 + fc2 -------------
__global__ __launch_bounds__(128)
void head_kernel(const float* __restrict__ cfcW, const float* __restrict__ cfcb,
                 const float* __restrict__ sfcW, const float* __restrict__ sfcb,
                 const float* __restrict__ fc1W, const float* __restrict__ fc1b,
                 const float* __restrict__ fc2W, const float* __restrict__ fc2b,
                 float* __restrict__ out) {
    __shared__ float sPool[384];
    __shared__ float sHg[768];
    __shared__ float sRed[128];
    const int b = blockIdx.x;
    const int tid = threadIdx.x;

    for (int i = tid; i < 384; i += 128) sPool[i] = g_pool[(size_t)b * 384 + i];
    __syncthreads();

    #pragma unroll
    for (int p = 0; p < 6; p++) {
        const bool slv = (p >= 3);
        const int e = slv ? (p - 3) : p;
        const float* W = slv ? sfcW : cfcW;
        const float* bias = slv ? sfcb : cfcb;
        const float* rep = sPool + (slv ? 192 : 0) + e * HALF;
        float acc = bias[e * DIM + tid];
        #pragma unroll 8
        for (int k = 0; k < HALF; k++)
            acc = fmaf(rep[k], W[(size_t)e * HALF * DIM + k * DIM + tid], acc);
        sHg[p * DIM + tid] = fmaxf(acc, 0.f);
    }
    __syncthreads();

    float acc = fc1b[tid];
    #pragma unroll 8
    for (int h = 0; h < 768; h++)
        acc = fmaf(sHg[h], fc1W[(size_t)h * DIM + tid], acc);
    float o1 = fmaxf(acc, 0.f);

    sRed[tid] = o1 * fc2W[tid];
    __syncthreads();
    if (tid < 64) sRed[tid] += sRed[tid + 64];
    __syncthreads();
    if (tid < 32) {
        float x = sRed[tid] + sRed[tid + 32];
        #pragma unroll
        for (int o = 16; o; o >>= 1) x += __shfl_down_sync(0xffffffffu, x, o);
        if (tid == 0) out[b] = x + fc2b[0];
    }
}

// ---------------- launch ----------------
extern "C" void kernel_launch(void* const* d_in, const int* in_sizes, int n_in,
                              void* d_out, int out_size) {
    const float* chr_x  = (const float*)d_in[0];
    const float* slv_x  = (const float*)d_in[1];
    const int*   chr_ei = (const int*)d_in[2];
    const int*   slv_ei = (const int*)d_in[3];
    const int*   chr_b  = (const int*)d_in[4];
    const int*   slv_b  = (const int*)d_in[5];
    const float* chr_W0 = (const float*)d_in[6];
    const float* chr_W1 = (const float*)d_in[7];
    const float* chr_W2 = (const float*)d_in[8];
    const float* slv_W0 = (const float*)d_in[9];
    const float* slv_W1 = (const float*)d_in[10];
    const float* slv_W2 = (const float*)d_in[11];
    const float* cfcW   = (const float*)d_in[12];
    const float* cfcb   = (const float*)d_in[13];
    const float* sfcW   = (const float*)d_in[14];
    const float* sfcb   = (const float*)d_in[15];
    const float* fc1W   = (const float*)d_in[16];
    const float* fc1b   = (const float*)d_in[17];
    const float* fc2W   = (const float*)d_in[18];
    const float* fc2b   = (const float*)d_in[19];
    float* out = (float*)d_out;

    __half *aggx, *buf1, *buf2;
    int* csr;
    cudaGetSymbolAddress((void**)&aggx, g_aggx);
    cudaGetSymbolAddress((void**)&buf1, g_buf1);
    cudaGetSymbolAddress((void**)&buf2, g_buf2);
    cudaGetSymbolAddress((void**)&csr, g_csr);

    // smem sizes (halves * 2 bytes)
    constexpr int SM01 = (2 * 128 * 72 + 64 * 136 + 128 * 136 + 128 * 136) * 2;  // 123904
    constexpr int SMG2 = (128 * 136 + 128 * 72) * 2;                              // 53248
    cudaFuncSetAttribute((const void*)gemm01_kernel,
                         cudaFuncAttributeMaxDynamicSharedMemorySize, SM01);
    cudaFuncSetAttribute((const void*)gather_gemm2_kernel,
                         cudaFuncAttributeMaxDynamicSharedMemorySize, SMG2);

    dim3 ggrid(50, ENS, 2);

    // ---- CSR build (g_deg zero at entry; re-zeroed inside gather64) ----
    count_deg_kernel<<<(ETOT + 255) / 256, 256>>>(chr_ei, slv_ei);   // + pool zero
    scan1_kernel<<<NB_SCAN, SCAN_BLK>>>(csr + ETOT - 128);  // raw block sums in csr tail
    scan2_kernel<<<1, 128>>>(csr + ETOT - 128);
    scan3_kernel<<<(NTOT + 255) / 256, 256>>>();
    fill_csr_kernel<<<(ETOT + 255) / 256, 256>>>(chr_ei, slv_ei);

    // ---- forward pass ----
    // 1) aggx = A x -> fp16 [N,64]
    gather64_kernel<<<(NTOT / 2 + 7) / 8, 256>>>(chr_x, slv_x, aggx);
    // 2+3) t1 = relu(aggx @ W0) @ W1 -> buf2 fp16 [N, 3*128] (h0 in smem only)
    gemm01_kernel<<<ggrid, 256, SM01>>>(aggx, buf2, chr_W0, slv_W0, chr_W1, slv_W1);
    // 4+5) t2 = relu(A t1)|e @ W2 -> buf1 fp16 [N, 3*64] (agg1 in smem only)
    gather_gemm2_kernel<<<ggrid, 256, SMG2>>>(buf2, buf1, chr_W2, slv_W2);
    // 6) pool[batch] += relu(A t2)
    gather192h_pool_kernel<<<(NTOT / 2 + 7) / 8, 256>>>(buf1, chr_b, slv_b);
    // 7) head
    head_kernel<<<B, 128>>>(cfcW, cfcb, sfcW, sfcb, fc1W, fc1b, fc2W, fc2b, out);
}

// round 12
// speedup vs baseline: 1.4679x; 1.4679x over previous
#include <cuda_runtime.h>
#include <cuda_bf16.h>
#include <cuda_fp16.h>

// ---------------- problem constants ----------------
constexpr int N_CHR = 50000, E_CHR = 500000;
constexpr int N_SLV = 30000, E_SLV = 300000;
constexpr int NTOT = N_CHR + N_SLV;      // 80000
constexpr int ETOT = E_CHR + E_SLV;      // 800000
constexpr int B    = 256;
constexpr int FEAT = 64;
constexpr int DIM  = 128;
constexpr int HALF = 64;
constexpr int ENS  = 3;
constexpr int SCAN_BLK = 1024;
constexpr int NB_SCAN = (NTOT + SCAN_BLK - 1) / SCAN_BLK;  // 79

// ---------------- scratch (device globals; no allocations allowed) --------
__device__ __align__(128) __half g_aggx[(size_t)NTOT * FEAT];
__device__ __align__(128) __half g_buf1[(size_t)NTOT * ENS * DIM];   // agg1 / t2
__device__ __align__(128) __half g_buf2[(size_t)NTOT * ENS * DIM];   // t1 / t2
__device__ float g_pool[(size_t)B * 2 * ENS * HALF];
__device__ int   g_deg[NTOT];        // ZERO at entry of every run (static init + re-zero in gather64)
__device__ int   g_incl[NTOT];
__device__ int   g_off[NTOT];
__device__ int   g_cursor[NTOT];     // after fill: end offset of each node
__device__ int   g_csr[ETOT];
__device__ int   g_bsumx[128];

// ---------------- helpers ----------------
__device__ __forceinline__ void red_add_v4(float* p, float4 v) {
    asm volatile("red.global.add.v4.f32 [%0], {%1,%2,%3,%4};"
                 :: "l"(p), "f"(v.x), "f"(v.y), "f"(v.z), "f"(v.w)
                 : "memory");
}

__device__ __forceinline__ void edge_sd(int e, const int* __restrict__ ec,
                                        const int* __restrict__ es, int& src, int& dst) {
    if (e < E_CHR) { src = ec[e]; dst = ec[E_CHR + e]; }
    else { int e2 = e - E_CHR; src = N_CHR + es[e2]; dst = N_CHR + es[E_SLV + e2]; }
}

__device__ __forceinline__ void ldsm_x4(unsigned* r, unsigned addr) {
    asm volatile("ldmatrix.sync.aligned.m8n8.x4.shared.b16 {%0,%1,%2,%3}, [%4];"
                 : "=r"(r[0]), "=r"(r[1]), "=r"(r[2]), "=r"(r[3]) : "r"(addr));
}
__device__ __forceinline__ void ldsm_x2t(unsigned* r, unsigned addr) {
    asm volatile("ldmatrix.sync.aligned.m8n8.x2.trans.shared.b16 {%0,%1}, [%2];"
                 : "=r"(r[0]), "=r"(r[1]) : "r"(addr));
}
__device__ __forceinline__ void mma16816(float* d, const unsigned* a, const unsigned* b) {
    asm volatile("mma.sync.aligned.m16n8k16.row.col.f32.f16.f16.f32 "
                 "{%0,%1,%2,%3}, {%4,%5,%6,%7}, {%8,%9}, {%0,%1,%2,%3};"
                 : "+f"(d[0]), "+f"(d[1]), "+f"(d[2]), "+f"(d[3])
                 : "r"(a[0]), "r"(a[1]), "r"(a[2]), "r"(a[3]), "r"(b[0]), "r"(b[1]));
}
__device__ __forceinline__ void cp_async16z(unsigned sa, const void* g, bool v) {
    int sz = v ? 16 : 0;
    asm volatile("cp.async.cg.shared.global [%0], [%1], 16, %2;"
                 :: "r"(sa), "l"(g), "r"(sz) : "memory");
}
__device__ __forceinline__ void cp_commit() {
    asm volatile("cp.async.commit_group;" ::: "memory");
}
__device__ __forceinline__ void cp_wait1() {
    asm volatile("cp.async.wait_group 1;" ::: "memory");
}
__device__ __forceinline__ unsigned pack2(float x, float y) {
    __half2 h = __floats2half2_rn(x, y);
    return *(unsigned*)&h;
}
__device__ __forceinline__ unsigned pack2r(float x, float y) {
    return pack2(fmaxf(x, 0.f), fmaxf(y, 0.f));
}
__device__ __forceinline__ void acc4(float* a, uint2 v) {
    float2 f0 = __half22float2(*(__half2*)&v.x);
    float2 f1 = __half22float2(*(__half2*)&v.y);
    a[0] += f0.x; a[1] += f0.y; a[2] += f1.x; a[3] += f1.y;
}
__device__ __forceinline__ void acc8(float* a, uint4 v) {
    acc4(a, make_uint2(v.x, v.y));
    acc4(a + 4, make_uint2(v.z, v.w));
}

// ---------------- CSR build ----------------
// also zeroes g_pool; requires g_deg == 0 at entry (maintained by gather64).
__global__ void count_deg_kernel(const int* __restrict__ ec, const int* __restrict__ es) {
    int e = blockIdx.x * blockDim.x + threadIdx.x;
    if (e < B * 384 / 4) ((float4*)g_pool)[e] = make_float4(0.f, 0.f, 0.f, 0.f);
    if (e >= ETOT) return;
    int src, dst; edge_sd(e, ec, es, src, dst);
    atomicAdd(&g_deg[dst], 1);
}

__global__ void scan1_kernel(int* __restrict__ bsum_raw) {
    __shared__ int s[SCAN_BLK];
    int tid = threadIdx.x;
    int i = blockIdx.x * SCAN_BLK + tid;
    int v = (i < NTOT) ? g_deg[i] : 0;
    s[tid] = v;
    __syncthreads();
    #pragma unroll
    for (int off = 1; off < SCAN_BLK; off <<= 1) {
        int t = (tid >= off) ? s[tid - off] : 0;
        __syncthreads();
        s[tid] += t;
        __syncthreads();
    }
    if (i < NTOT) g_incl[i] = s[tid];
    if (tid == SCAN_BLK - 1) bsum_raw[blockIdx.x] = s[tid];
}

__global__ void scan2_kernel(const int* __restrict__ bsum_raw) {
    __shared__ int s[128];
    int tid = threadIdx.x;
    int v = (tid < NB_SCAN) ? bsum_raw[tid] : 0;
    s[tid] = v;
    __syncthreads();
    #pragma unroll
    for (int off = 1; off < 128; off <<= 1) {
        int t = (tid >= off) ? s[tid - off] : 0;
        __syncthreads();
        s[tid] += t;
        __syncthreads();
    }
    g_bsumx[tid] = s[tid] - v;  // exclusive
}

__global__ void scan3_kernel() {
    int i = blockIdx.x * blockDim.x + threadIdx.x;
    if (i >= NTOT) return;
    int start = g_incl[i] - g_deg[i] + g_bsumx[i / SCAN_BLK];
    g_off[i] = start;
    g_cursor[i] = start;
}

__global__ void fill_csr_kernel(const int* __restrict__ ec, const int* __restrict__ es) {
    int e = blockIdx.x * blockDim.x + threadIdx.x;
    if (e >= ETOT) return;
    int src, dst; edge_sd(e, ec, es, src, dst);
    int pos = atomicAdd(&g_cursor[dst], 1);
    g_csr[pos] = src;
}

// ---------------- gathers (2 nodes/warp, 1-ahead prefetch) ----------------
// first aggregation over raw fp32 features -> fp16 output; also re-zeroes g_deg.
__global__ __launch_bounds__(256)
void gather64_kernel(const float* __restrict__ xchr, const float* __restrict__ xslv,
                     __half* __restrict__ out) {
    int lane = threadIdx.x & 31;
    int sub = lane >> 4;
    int l = lane & 15;
    unsigned hmask = 0xffffu << (sub * 16);
    int node = ((blockIdx.x * blockDim.x + threadIdx.x) >> 5) * 2 + sub;
    if (node >= NTOT) return;
    int start = g_off[node], deg = g_cursor[node] - start;
    if (l == 0) g_deg[node] = 0;
    float4 a = make_float4(0.f, 0.f, 0.f, 0.f);
    for (int kb = 0; kb < deg; kb += 16) {
        int idx = (kb + l < deg) ? g_csr[start + kb + l] : 0;
        int m = min(16, deg - kb);
        int s = __shfl_sync(hmask, idx, 0, 16);
        const float4* sr = (s < N_CHR) ? (const float4*)(xchr + (size_t)s * 64)
                                       : (const float4*)(xslv + (size_t)(s - N_CHR) * 64);
        float4 p = sr[l];
        for (int k = 0; k < m; k++) {
            float4 c = p;
            if (k + 1 < m) {
                int s2 = __shfl_sync(hmask, idx, k + 1, 16);
                const float4* nr = (s2 < N_CHR) ? (const float4*)(xchr + (size_t)s2 * 64)
                                                : (const float4*)(xslv + (size_t)(s2 - N_CHR) * 64);
                p = nr[l];
            }
            a.x += c.x; a.y += c.y; a.z += c.z; a.w += c.w;
        }
    }
    uint2 u; u.x = pack2(a.x, a.y); u.y = pack2(a.z, a.w);
    *(uint2*)(out + (size_t)node * 64 + l * 4) = u;
}

// 384-wide aggregation over fp16 rows -> relu -> fp16 output. 2 nodes/warp.
__global__ __launch_bounds__(256)
void gather384h_kernel(const __half* __restrict__ in, __half* __restrict__ out) {
    int lane = threadIdx.x & 31;
    int sub = lane >> 4;
    int l = lane & 15;
    unsigned hmask = 0xffffu << (sub * 16);
    int node = ((blockIdx.x * blockDim.x + threadIdx.x) >> 5) * 2 + sub;
    if (node >= NTOT) return;
    int start = g_off[node], deg = g_cursor[node] - start;
    float a[24];
    #pragma unroll
    for (int i = 0; i < 24; i++) a[i] = 0.f;
    for (int kb = 0; kb < deg; kb += 16) {
        int idx = (kb + l < deg) ? g_csr[start + kb + l] : 0;
        int m = min(16, deg - kb);
        int s = __shfl_sync(hmask, idx, 0, 16);
        const uint4* sr = (const uint4*)(in + (size_t)s * 384);
        uint4 p0 = sr[l], p1 = sr[l + 16], p2 = sr[l + 32];
        for (int k = 0; k < m; k++) {
            uint4 c0 = p0, c1 = p1, c2 = p2;
            if (k + 1 < m) {
                int s2 = __shfl_sync(hmask, idx, k + 1, 16);
                const uint4* nr = (const uint4*)(in + (size_t)s2 * 384);
                p0 = nr[l]; p1 = nr[l + 16]; p2 = nr[l + 32];
            }
            acc8(a, c0); acc8(a + 8, c1); acc8(a + 16, c2);
        }
    }
    uint4* orow = (uint4*)(out + (size_t)node * 384);
    uint4 o;
    o.x = pack2r(a[0], a[1]);   o.y = pack2r(a[2], a[3]);
    o.z = pack2r(a[4], a[5]);   o.w = pack2r(a[6], a[7]);
    orow[l] = o;
    o.x = pack2r(a[8], a[9]);   o.y = pack2r(a[10], a[11]);
    o.z = pack2r(a[12], a[13]); o.w = pack2r(a[14], a[15]);
    orow[l + 16] = o;
    o.x = pack2r(a[16], a[17]); o.y = pack2r(a[18], a[19]);
    o.z = pack2r(a[20], a[21]); o.w = pack2r(a[22], a[23]);
    orow[l + 32] = o;
}

// layer-2 aggregation (192-wide fp16 rows) + relu + global_add_pool. 2 nodes/warp.
__global__ __launch_bounds__(256)
void gather192h_pool_kernel(const __half* __restrict__ in,
                            const int* __restrict__ bchr, const int* __restrict__ bslv) {
    int lane = threadIdx.x & 31;
    int sub = lane >> 4;
    int l = lane & 15;
    unsigned hmask = 0xffffu << (sub * 16);
    int node = ((blockIdx.x * blockDim.x + threadIdx.x) >> 5) * 2 + sub;
    if (node >= NTOT) return;
    int start = g_off[node], deg = g_cursor[node] - start;
    float a[12];
    #pragma unroll
    for (int i = 0; i < 12; i++) a[i] = 0.f;
    for (int kb = 0; kb < deg; kb += 16) {
        int idx = (kb + l < deg) ? g_csr[start + kb + l] : 0;
        int m = min(16, deg - kb);
        int s = __shfl_sync(hmask, idx, 0, 16);
        const uint2* sr = (const uint2*)(in + (size_t)s * 192);
        uint2 p0 = sr[l], p1 = sr[l + 16], p2 = sr[l + 32];
        for (int k = 0; k < m; k++) {
            uint2 c0 = p0, c1 = p1, c2 = p2;
            if (k + 1 < m) {
                int s2 = __shfl_sync(hmask, idx, k + 1, 16);
                const uint2* nr = (const uint2*)(in + (size_t)s2 * 192);
                p0 = nr[l]; p1 = nr[l + 16]; p2 = nr[l + 32];
            }
            acc4(a, c0); acc4(a + 4, c1); acc4(a + 8, c2);
        }
    }
    #pragma unroll
    for (int i = 0; i < 12; i++) a[i] = fmaxf(a[i], 0.f);
    int b, colbase;
    if (node < N_CHR) { b = bchr[node]; colbase = 0; }
    else              { b = bslv[node - N_CHR]; colbase = 192; }
    float* prow = g_pool + (size_t)b * 384 + colbase;
    red_add_v4(prow + l * 4,       make_float4(a[0], a[1], a[2], a[3]));
    red_add_v4(prow + 64 + l * 4,  make_float4(a[4], a[5], a[6], a[7]));
    red_add_v4(prow + 128 + l * 4, make_float4(a[8], a[9], a[10], a[11]));
}

// ---------------- fused GEMM0+GEMM1: t1 = relu(aggx@W0) @ W1 --------------
// h0 tile lives only in smem. 256 threads, tile = 128 rows.
__global__ __launch_bounds__(256, 1)
void gemm01_kernel(const __half* __restrict__ in, __half* __restrict__ out,
                   const float* __restrict__ W0c, const float* __restrict__ W0s,
                   const float* __restrict__ W1c, const float* __restrict__ W1s) {
    constexpr int TR = 128;
    constexpr int LDA = 72;    // 64 + 8
    constexpr int LDW = 136;   // 128 + 8
    constexpr int ABUF = TR * LDA;

    extern __shared__ __half hsm[];
    __half* sA  = hsm;                         // [2][128][72]
    __half* sW0 = hsm + 2 * ABUF;              // [64][136]
    __half* sW1 = sW0 + 64 * LDW;              // [128][136]
    __half* sH  = sW1 + 128 * LDW;             // [128][136]

    const int e = blockIdx.y;
    const int branch = blockIdx.z;
    const int tid = threadIdx.x;
    const int wid = tid >> 5;
    const int lane = tid & 31;
    const int rowgrp = wid >> 1;   // 4 groups of 32 rows
    const int colgrp = wid & 1;    // 2 groups of 64 cols

    const int base  = branch ? N_CHR : 0;
    const int nrows = branch ? N_SLV : N_CHR;
    const int ntiles = (nrows + TR - 1) / TR;

    // weights fp32 -> fp16 smem [k][n]
    {
        const float* W0 = (branch ? W0s : W0c) + (size_t)e * 64 * 128;
        for (int idx = tid; idx < 64 * 128 / 4; idx += 256) {
            int k = idx / 32, c = idx % 32;
            float4 w = ((const float4*)W0)[idx];
            uint2 u; u.x = pack2(w.x, w.y); u.y = pack2(w.z, w.w);
            *(uint2*)(sW0 + k * LDW + c * 4) = u;
        }
        const float* W1 = (branch ? W1s : W1c) + (size_t)e * 128 * 128;
        for (int idx = tid; idx < 128 * 128 / 4; idx += 256) {
            int k = idx / 32, c = idx % 32;
            float4 w = ((const float4*)W1)[idx];
            uint2 u; u.x = pack2(w.x, w.y); u.y = pack2(w.z, w.w);
            *(uint2*)(sW1 + k * LDW + c * 4) = u;
        }
    }

    unsigned sa_base = (unsigned)__cvta_generic_to_shared(sA);
    unsigned sw0_base = (unsigned)__cvta_generic_to_shared(sW0);
    unsigned sw1_base = (unsigned)__cvta_generic_to_shared(sW1);
    unsigned sh_base = (unsigned)__cvta_generic_to_shared(sH);

    auto load_tile = [&](int t, int buf) {
        int row0 = base + t * TR;
        for (int i = tid; i < TR * 8; i += 256) {   // 8 uint4 per 64-wide row
            int r = i >> 3, c = i & 7;
            bool valid = (row0 + r) < base + nrows;
            int rr = valid ? (row0 + r) : 0;
            const void* g = in + (size_t)rr * 64 + c * 8;
            cp_async16z(sa_base + (unsigned)(buf * ABUF + r * LDA + c * 8) * 2, g, valid);
        }
    };

    int t0 = blockIdx.x;
    if (t0 < ntiles) load_tile(t0, 0);
    cp_commit();

    int bi = 0;
    for (int t = t0; t < ntiles; t += gridDim.x, bi ^= 1) {
        int tn = t + gridDim.x;
        if (tn < ntiles) load_tile(tn, bi ^ 1);
        cp_commit();
        cp_wait1();
        __syncthreads();

        int row0 = base + t * TR;
        int rcnt = min(TR, base + nrows - row0);
        unsigned abuf = sa_base + (unsigned)(bi * ABUF) * 2;
        int lrow = lane >> 2, lcol = (lane & 3) * 2;

        // ---- MMA1: h0 = relu(A @ W0) -> sH ----
        {
            float acc[2][8][4];
            #pragma unroll
            for (int mt = 0; mt < 2; mt++)
                #pragma unroll
                for (int nt = 0; nt < 8; nt++)
                    #pragma unroll
                    for (int q = 0; q < 4; q++) acc[mt][nt][q] = 0.f;
            #pragma unroll
            for (int ks = 0; ks < 4; ks++) {   // K = 64
                unsigned a[2][4];
                #pragma unroll
                for (int mt = 0; mt < 2; mt++) {
                    int r = rowgrp * 32 + mt * 16 + (lane & 15);
                    int c = ks * 16 + (lane >> 4) * 8;
                    ldsm_x4(a[mt], abuf + (unsigned)(r * LDA + c) * 2);
                }
                #pragma unroll
                for (int nt = 0; nt < 8; nt++) {
                    unsigned b[2];
                    int rk = ks * 16 + (lane & 15);
                    int cn = colgrp * 64 + nt * 8;
                    ldsm_x2t(b, sw0_base + (unsigned)(rk * LDW + cn) * 2);
                    #pragma unroll
                    for (int mt = 0; mt < 2; mt++)
                        mma16816(acc[mt][nt], a[mt], b);
                }
            }
            // epilogue 1: relu + fp16 into sH (unconditional; invalid rows are 0)
            #pragma unroll
            for (int mt = 0; mt < 2; mt++) {
                #pragma unroll
                for (int nt = 0; nt < 8; nt++) {
                    int col = colgrp * 64 + nt * 8 + lcol;
                    int r1 = rowgrp * 32 + mt * 16 + lrow;
                    *(__half2*)(sH + r1 * LDW + col) =
                        __floats2half2_rn(fmaxf(acc[mt][nt][0], 0.f), fmaxf(acc[mt][nt][1], 0.f));
                    *(__half2*)(sH + (r1 + 8) * LDW + col) =
                        __floats2half2_rn(fmaxf(acc[mt][nt][2], 0.f), fmaxf(acc[mt][nt][3], 0.f));
                }
            }
        }
        __syncthreads();

        // ---- MMA2: t1 = h0 @ W1 -> gmem ----
        {
            float acc[2][8][4];
            #pragma unroll
            for (int mt = 0; mt < 2; mt++)
                #pragma unroll
                for (int nt = 0; nt < 8; nt++)
                    #pragma unroll
                    for (int q = 0; q < 4; q++) acc[mt][nt][q] = 0.f;
            #pragma unroll
            for (int ks = 0; ks < 8; ks++) {   // K = 128
                unsigned a[2][4];
                #pragma unroll
                for (int mt = 0; mt < 2; mt++) {
                    int r = rowgrp * 32 + mt * 16 + (lane & 15);
                    int c = ks * 16 + (lane >> 4) * 8;
                    ldsm_x4(a[mt], sh_base + (unsigned)(r * LDW + c) * 2);
                }
                #pragma unroll
                for (int nt = 0; nt < 8; nt++) {
                    unsigned b[2];
                    int rk = ks * 16 + (lane & 15);
                    int cn = colgrp * 64 + nt * 8;
                    ldsm_x2t(b, sw1_base + (unsigned)(rk * LDW + cn) * 2);
                    #pragma unroll
                    for (int mt = 0; mt < 2; mt++)
                        mma16816(acc[mt][nt], a[mt], b);
                }
            }
            #pragma unroll
            for (int mt = 0; mt < 2; mt++) {
                #pragma unroll
                for (int nt = 0; nt < 8; nt++) {
                    int col = colgrp * 64 + nt * 8 + lcol;
                    int r1 = rowgrp * 32 + mt * 16 + lrow;
                    if (r1 < rcnt)
                        *(__half2*)(out + (size_t)(row0 + r1) * 384 + e * 128 + col) =
                            __floats2half2_rn(acc[mt][nt][0], acc[mt][nt][1]);
                    if (r1 + 8 < rcnt)
                        *(__half2*)(out + (size_t)(row0 + r1 + 8) * 384 + e * 128 + col) =
                            __floats2half2_rn(acc[mt][nt][2], acc[mt][nt][3]);
                }
            }
        }
        __syncthreads();
    }
}

// ---------------- fp16 tensor-core GEMM (cp.async double-buffered) --------
// (used for GEMM3: t2 = agg1 @ W2)
template<int K, int MOUT, bool RELU_OUT>
__global__ __launch_bounds__(256, 1)
void hgemm_kernel(const __half* __restrict__ in, __half* __restrict__ out,
                  const float* __restrict__ Wc, const float* __restrict__ Ws,
                  int in_stride, int in_eoff, int out_stride, int out_eoff) {
    constexpr int TR = 128;
    constexpr int CGS = MOUT / 64;
    constexpr int RGS = 8 / CGS;
    constexpr int WM = TR / RGS;
    constexpr int MT = WM / 16;
    constexpr int LDA = K + 8;
    constexpr int LDB = MOUT + 8;
    constexpr int KS = K / 16;
    constexpr int ABUF = TR * LDA;

    extern __shared__ __half hsm[];
    __half* sA = hsm;
    __half* sB = hsm + 2 * ABUF;

    const int e = blockIdx.y;
    const int branch = blockIdx.z;
    const int tid = threadIdx.x;
    const int wid = tid >> 5;
    const int lane = tid & 31;
    const int rowgrp = wid / CGS;
    const int colgrp = wid % CGS;

    const int base  = branch ? N_CHR : 0;
    const int nrows = branch ? N_SLV : N_CHR;
    const int ntiles = (nrows + TR - 1) / TR;
    const float* W = (branch ? Ws : Wc) + (size_t)e * K * MOUT;

    for (int idx = tid; idx < K * MOUT / 4; idx += 256) {
        int k = idx / (MOUT / 4), c = idx % (MOUT / 4);
        float4 w = ((const float4*)W)[idx];
        uint2 u; u.x = pack2(w.x, w.y); u.y = pack2(w.z, w.w);
        *(uint2*)(sB + k * LDB + c * 4) = u;
    }

    unsigned sa_base = (unsigned)__cvta_generic_to_shared(sA);
    unsigned sb_base = (unsigned)__cvta_generic_to_shared(sB);

    auto load_tile = [&](int t, int buf) {
        int row0 = base + t * TR;
        constexpr int C8 = TR * (K / 8);
        for (int i = tid; i < C8; i += 256) {
            int r = i / (K / 8), c = i % (K / 8);
            bool valid = (row0 + r) < base + nrows;
            int rr = valid ? (row0 + r) : base;
            const void* g = in + (size_t)rr * in_stride + (size_t)e * in_eoff + c * 8;
            cp_async16z(sa_base + (unsigned)(buf * ABUF + r * LDA + c * 8) * 2, g, valid);
        }
    };

    int t0 = blockIdx.x;
    if (t0 < ntiles) load_tile(t0, 0);
    cp_commit();

    int bi = 0;
    for (int t = t0; t < ntiles; t += gridDim.x, bi ^= 1) {
        int tn = t + gridDim.x;
        if (tn < ntiles) load_tile(tn, bi ^ 1);
        cp_commit();
        cp_wait1();
        __syncthreads();

        int row0 = base + t * TR;
        int rcnt = min(TR, base + nrows - row0);
        unsigned abuf = sa_base + (unsigned)(bi * ABUF) * 2;

        float acc[MT][8][4];
        #pragma unroll
        for (int mt = 0; mt < MT; mt++)
            #pragma unroll
            for (int nt = 0; nt < 8; nt++)
                #pragma unroll
                for (int q = 0; q < 4; q++) acc[mt][nt][q] = 0.f;

        #pragma unroll
        for (int ks = 0; ks < KS; ks++) {
            unsigned a[MT][4];
            #pragma unroll
            for (int mt = 0; mt < MT; mt++) {
                int r = rowgrp * WM + mt * 16 + (lane & 15);
                int c = ks * 16 + (lane >> 4) * 8;
                ldsm_x4(a[mt], abuf + (unsigned)(r * LDA + c) * 2);
            }
            #pragma unroll
            for (int nt = 0; nt < 8; nt++) {
                unsigned b[2];
                int rk = ks * 16 + (lane & 15);
                int cn = colgrp * 64 + nt * 8;
                ldsm_x2t(b, sb_base + (unsigned)(rk * LDB + cn) * 2);
                #pragma unroll
                for (int mt = 0; mt < MT; mt++)
                    mma16816(acc[mt][nt], a[mt], b);
            }
        }

        int lrow = lane >> 2, lcol = (lane & 3) * 2;
        #pragma unroll
        for (int mt = 0; mt < MT; mt++) {
            #pragma unroll
            for (int nt = 0; nt < 8; nt++) {
                int col = colgrp * 64 + nt * 8 + lcol;
                int r1 = rowgrp * WM + mt * 16 + lrow;
                float x0 = acc[mt][nt][0], x1 = acc[mt][nt][1];
                float x2 = acc[mt][nt][2], x3 = acc[mt][nt][3];
                if (RELU_OUT) {
                    x0 = fmaxf(x0, 0.f); x1 = fmaxf(x1, 0.f);
                    x2 = fmaxf(x2, 0.f); x3 = fmaxf(x3, 0.f);
                }
                if (r1 < rcnt) {
                    __half2 h = __floats2half2_rn(x0, x1);
                    *(__half2*)(out + (size_t)(row0 + r1) * out_stride + (size_t)e * out_eoff + col) = h;
                }
                if (r1 + 8 < rcnt) {
                    __half2 h = __floats2half2_rn(x2, x3);
                    *(__half2*)(out + (size_t)(row0 + r1 + 8) * out_stride + (size_t)e * out_eoff + col) = h;
                }
            }
        }
        __syncthreads();
    }
}

// ---------------- head: projection heads + concat + fc1 + fc2 -------------
__global__ __launch_bounds__(128)
void head_kernel(const float* __restrict__ cfcW, const float* __restrict__ cfcb,
                 const float* __restrict__ sfcW, const float* __restrict__ sfcb,
                 const float* __restrict__ fc1W, const float* __restrict__ fc1b,
                 const float* __restrict__ fc2W, const float* __restrict__ fc2b,
                 float* __restrict__ out) {
    __shared__ float sPool[384];
    __shared__ float sHg[768];
    __shared__ float sRed[128];
    const int b = blockIdx.x;
    const int tid = threadIdx.x;

    for (int i = tid; i < 384; i += 128) sPool[i] = g_pool[(size_t)b * 384 + i];
    __syncthreads();

    #pragma unroll
    for (int p = 0; p < 6; p++) {
        const bool slv = (p >= 3);
        const int e = slv ? (p - 3) : p;
        const float* W = slv ? sfcW : cfcW;
        const float* bias = slv ? sfcb : cfcb;
        const float* rep = sPool + (slv ? 192 : 0) + e * HALF;
        float acc = bias[e * DIM + tid];
        #pragma unroll 8
        for (int k = 0; k < HALF; k++)
            acc = fmaf(rep[k], W[(size_t)e * HALF * DIM + k * DIM + tid], acc);
        sHg[p * DIM + tid] = fmaxf(acc, 0.f);
    }
    __syncthreads();

    float acc = fc1b[tid];
    #pragma unroll 8
    for (int h = 0; h < 768; h++)
        acc = fmaf(sHg[h], fc1W[(size_t)h * DIM + tid], acc);
    float o1 = fmaxf(acc, 0.f);

    sRed[tid] = o1 * fc2W[tid];
    __syncthreads();
    if (tid < 64) sRed[tid] += sRed[tid + 64];
    __syncthreads();
    if (tid < 32) {
        float x = sRed[tid] + sRed[tid + 32];
        #pragma unroll
        for (int o = 16; o; o >>= 1) x += __shfl_down_sync(0xffffffffu, x, o);
        if (tid == 0) out[b] = x + fc2b[0];
    }
}

// ---------------- launch ----------------
extern "C" void kernel_launch(void* const* d_in, const int* in_sizes, int n_in,
                              void* d_out, int out_size) {
    const float* chr_x  = (const float*)d_in[0];
    const float* slv_x  = (const float*)d_in[1];
    const int*   chr_ei = (const int*)d_in[2];
    const int*   slv_ei = (const int*)d_in[3];
    const int*   chr_b  = (const int*)d_in[4];
    const int*   slv_b  = (const int*)d_in[5];
    const float* chr_W0 = (const float*)d_in[6];
    const float* chr_W1 = (const float*)d_in[7];
    const float* chr_W2 = (const float*)d_in[8];
    const float* slv_W0 = (const float*)d_in[9];
    const float* slv_W1 = (const float*)d_in[10];
    const float* slv_W2 = (const float*)d_in[11];
    const float* cfcW   = (const float*)d_in[12];
    const float* cfcb   = (const float*)d_in[13];
    const float* sfcW   = (const float*)d_in[14];
    const float* sfcb   = (const float*)d_in[15];
    const float* fc1W   = (const float*)d_in[16];
    const float* fc1b   = (const float*)d_in[17];
    const float* fc2W   = (const float*)d_in[18];
    const float* fc2b   = (const float*)d_in[19];
    float* out = (float*)d_out;

    __half *aggx, *buf1, *buf2;
    int* csr;
    cudaGetSymbolAddress((void**)&aggx, g_aggx);
    cudaGetSymbolAddress((void**)&buf1, g_buf1);
    cudaGetSymbolAddress((void**)&buf2, g_buf2);
    cudaGetSymbolAddress((void**)&csr, g_csr);

    // smem sizes
    constexpr int SM01 = (2 * 128 * 72 + 64 * 136 + 128 * 136 + 128 * 136) * 2;  // 123904
    constexpr int SM2  = (2 * 128 * 136 + 128 * 72) * 2;                          // 88064
    cudaFuncSetAttribute((const void*)gemm01_kernel,
                         cudaFuncAttributeMaxDynamicSharedMemorySize, SM01);
    cudaFuncSetAttribute((const void*)hgemm_kernel<128, 64, false>,
                         cudaFuncAttributeMaxDynamicSharedMemorySize, SM2);

    dim3 ggrid(50, ENS, 2);

    // ---- CSR build (g_deg zero at entry; re-zeroed inside gather64) ----
    count_deg_kernel<<<(ETOT + 255) / 256, 256>>>(chr_ei, slv_ei);   // + pool zero
    scan1_kernel<<<NB_SCAN, SCAN_BLK>>>(csr + ETOT - 128);  // raw block sums in csr tail
    scan2_kernel<<<1, 128>>>(csr + ETOT - 128);
    scan3_kernel<<<(NTOT + 255) / 256, 256>>>();
    fill_csr_kernel<<<(ETOT + 255) / 256, 256>>>(chr_ei, slv_ei);

    // ---- forward pass ----
    // 1) aggx = A x -> fp16 [N,64]
    gather64_kernel<<<(NTOT / 2 + 7) / 8, 256>>>(chr_x, slv_x, aggx);
    // 2+3) t1 = relu(aggx @ W0) @ W1 -> buf2 fp16 [N, 3*128] (h0 smem-only)
    gemm01_kernel<<<ggrid, 256, SM01>>>(aggx, buf2, chr_W0, slv_W0, chr_W1, slv_W1);
    // 4) agg1 = relu(A t1) -> buf1 fp16 [N, 3*128]
    gather384h_kernel<<<(NTOT / 2 + 7) / 8, 256>>>(buf2, buf1);
    // 5) t2 = agg1 @ W2 -> buf2 fp16 [N, 3*64]
    hgemm_kernel<128, 64, false><<<ggrid, 256, SM2>>>(
        buf1, buf2, chr_W2, slv_W2, ENS * DIM, DIM, ENS * HALF, HALF);
    // 6) pool[batch] += relu(A t2)
    gather192h_pool_kernel<<<(NTOT / 2 + 7) / 8, 256>>>(buf2, chr_b, slv_b);
    // 7) head
    head_kernel<<<B, 128>>>(cfcW, cfcb, sfcW, sfcb, fc1W, fc1b, fc2W, fc2b, out);
}

// round 13
// speedup vs baseline: 1.4762x; 1.0056x over previous
#include <cuda_runtime.h>
#include <cuda_bf16.h>
#include <cuda_fp16.h>

// ---------------- problem constants ----------------
constexpr int N_CHR = 50000, E_CHR = 500000;
constexpr int N_SLV = 30000, E_SLV = 300000;
constexpr int NTOT = N_CHR + N_SLV;      // 80000
constexpr int ETOT = E_CHR + E_SLV;      // 800000
constexpr int B    = 256;
constexpr int FEAT = 64;
constexpr int DIM  = 128;
constexpr int HALF = 64;
constexpr int ENS  = 3;
constexpr int SCAN_BLK = 1024;
constexpr int NB_SCAN = (NTOT + SCAN_BLK - 1) / SCAN_BLK;  // 79

// ---------------- scratch (device globals; no allocations allowed) --------
__device__ __align__(128) __half g_aggx[(size_t)NTOT * FEAT];
__device__ __align__(128) __half g_buf1[(size_t)NTOT * ENS * DIM];   // agg1 / t2
__device__ __align__(128) __half g_buf2[(size_t)NTOT * ENS * DIM];   // t1
__device__ float g_pool[(size_t)B * 2 * ENS * HALF];
__device__ int   g_deg[NTOT];        // ZERO at entry of every run (static init + re-zero in gather64)
__device__ int   g_incl[NTOT];
__device__ int   g_off[NTOT];
__device__ int   g_cursor[NTOT];     // after fill: end offset of each node
__device__ int   g_csr[ETOT];

// ---------------- helpers ----------------
__device__ __forceinline__ void red_add_v4(float* p, float4 v) {
    asm volatile("red.global.add.v4.f32 [%0], {%1,%2,%3,%4};"
                 :: "l"(p), "f"(v.x), "f"(v.y), "f"(v.z), "f"(v.w)
                 : "memory");
}

__device__ __forceinline__ void edge_sd(int e, const int* __restrict__ ec,
                                        const int* __restrict__ es, int& src, int& dst) {
    if (e < E_CHR) { src = ec[e]; dst = ec[E_CHR + e]; }
    else { int e2 = e - E_CHR; src = N_CHR + es[e2]; dst = N_CHR + es[E_SLV + e2]; }
}

__device__ __forceinline__ void ldsm_x4(unsigned* r, unsigned addr) {
    asm volatile("ldmatrix.sync.aligned.m8n8.x4.shared.b16 {%0,%1,%2,%3}, [%4];"
                 : "=r"(r[0]), "=r"(r[1]), "=r"(r[2]), "=r"(r[3]) : "r"(addr));
}
__device__ __forceinline__ void ldsm_x2t(unsigned* r, unsigned addr) {
    asm volatile("ldmatrix.sync.aligned.m8n8.x2.trans.shared.b16 {%0,%1}, [%2];"
                 : "=r"(r[0]), "=r"(r[1]) : "r"(addr));
}
__device__ __forceinline__ void mma16816(float* d, const unsigned* a, const unsigned* b) {
    asm volatile("mma.sync.aligned.m16n8k16.row.col.f32.f16.f16.f32 "
                 "{%0,%1,%2,%3}, {%4,%5,%6,%7}, {%8,%9}, {%0,%1,%2,%3};"
                 : "+f"(d[0]), "+f"(d[1]), "+f"(d[2]), "+f"(d[3])
                 : "r"(a[0]), "r"(a[1]), "r"(a[2]), "r"(a[3]), "r"(b[0]), "r"(b[1]));
}
__device__ __forceinline__ void cp_async16z(unsigned sa, const void* g, bool v) {
    int sz = v ? 16 : 0;
    asm volatile("cp.async.cg.shared.global [%0], [%1], 16, %2;"
                 :: "r"(sa), "l"(g), "r"(sz) : "memory");
}
__device__ __forceinline__ void cp_commit() {
    asm volatile("cp.async.commit_group;" ::: "memory");
}
__device__ __forceinline__ void cp_wait1() {
    asm volatile("cp.async.wait_group 1;" ::: "memory");
}
__device__ __forceinline__ unsigned pack2(float x, float y) {
    __half2 h = __floats2half2_rn(x, y);
    return *(unsigned*)&h;
}
__device__ __forceinline__ unsigned pack2r(float x, float y) {
    return pack2(fmaxf(x, 0.f), fmaxf(y, 0.f));
}
__device__ __forceinline__ void acc4(float* a, uint2 v) {
    float2 f0 = __half22float2(*(__half2*)&v.x);
    float2 f1 = __half22float2(*(__half2*)&v.y);
    a[0] += f0.x; a[1] += f0.y; a[2] += f1.x; a[3] += f1.y;
}
__device__ __forceinline__ void acc8(float* a, uint4 v) {
    acc4(a, make_uint2(v.x, v.y));
    acc4(a + 4, make_uint2(v.z, v.w));
}

// ---------------- CSR build ----------------
// also zeroes g_pool; requires g_deg == 0 at entry (maintained by gather64).
__global__ void count_deg_kernel(const int* __restrict__ ec, const int* __restrict__ es) {
    int e = blockIdx.x * blockDim.x + threadIdx.x;
    if (e < B * 384 / 4) ((float4*)g_pool)[e] = make_float4(0.f, 0.f, 0.f, 0.f);
    if (e >= ETOT) return;
    int src, dst; edge_sd(e, ec, es, src, dst);
    atomicAdd(&g_deg[dst], 1);
}

// warp-shuffle inclusive scan per 1024-block; writes block sums.
__global__ __launch_bounds__(SCAN_BLK)
void scan1_kernel(int* __restrict__ bsum_raw) {
    __shared__ int warpsum[32];
    int tid = threadIdx.x, lane = tid & 31, wid = tid >> 5;
    int i = blockIdx.x * SCAN_BLK + tid;
    int v = (i < NTOT) ? g_deg[i] : 0;
    int x = v;
    #pragma unroll
    for (int o = 1; o < 32; o <<= 1) {
        int t = __shfl_up_sync(0xffffffffu, x, o);
        if (lane >= o) x += t;
    }
    if (lane == 31) warpsum[wid] = x;
    __syncthreads();
    if (wid == 0) {
        int y = warpsum[lane];
        #pragma unroll
        for (int o = 1; o < 32; o <<= 1) {
            int t = __shfl_up_sync(0xffffffffu, y, o);
            if (lane >= o) y += t;
        }
        warpsum[lane] = y;
    }
    __syncthreads();
    int incl = x + (wid ? warpsum[wid - 1] : 0);
    if (i < NTOT) g_incl[i] = incl;
    if (tid == SCAN_BLK - 1) bsum_raw[blockIdx.x] = incl;
}

// merged scan2+scan3: each block scans the 79 block sums, then writes offsets
__global__ void scan23_kernel(const int* __restrict__ bsum_raw) {
    __shared__ int s[128];
    __shared__ int r[128];
    int tid = threadIdx.x;
    if (tid < 128) {
        int v = (tid < NB_SCAN) ? bsum_raw[tid] : 0;
        s[tid] = v; r[tid] = v;
    }
    __syncthreads();
    #pragma unroll
    for (int off = 1; off < 128; off <<= 1) {
        int t = (tid < 128 && tid >= off) ? s[tid - off] : 0;
        __syncthreads();
        if (tid < 128) s[tid] += t;
        __syncthreads();
    }
    int i = blockIdx.x * blockDim.x + tid;
    if (i < NTOT) {
        int b = i >> 10;
        int start = g_incl[i] - g_deg[i] + (s[b] - r[b]);
        g_off[i] = start;
        g_cursor[i] = start;
    }
}

__global__ void fill_csr_kernel(const int* __restrict__ ec, const int* __restrict__ es) {
    int e = blockIdx.x * blockDim.x + threadIdx.x;
    if (e >= ETOT) return;
    int src, dst; edge_sd(e, ec, es, src, dst);
    int pos = atomicAdd(&g_cursor[dst], 1);
    g_csr[pos] = src;
}

// ---------------- gathers (2 nodes/warp, 1-ahead prefetch) ----------------
// first aggregation over raw fp32 features -> fp16 output; also re-zeroes g_deg.
__global__ __launch_bounds__(256)
void gather64_kernel(const float* __restrict__ xchr, const float* __restrict__ xslv,
                     __half* __restrict__ out) {
    int lane = threadIdx.x & 31;
    int sub = lane >> 4;
    int l = lane & 15;
    unsigned hmask = 0xffffu << (sub * 16);
    int node = ((blockIdx.x * blockDim.x + threadIdx.x) >> 5) * 2 + sub;
    if (node >= NTOT) return;
    int start = g_off[node], deg = g_cursor[node] - start;
    if (l == 0) g_deg[node] = 0;
    float4 a = make_float4(0.f, 0.f, 0.f, 0.f);
    for (int kb = 0; kb < deg; kb += 16) {
        int idx = (kb + l < deg) ? g_csr[start + kb + l] : 0;
        int m = min(16, deg - kb);
        int s = __shfl_sync(hmask, idx, 0, 16);
        const float4* sr = (s < N_CHR) ? (const float4*)(xchr + (size_t)s * 64)
                                       : (const float4*)(xslv + (size_t)(s - N_CHR) * 64);
        float4 p = sr[l];
        for (int k = 0; k < m; k++) {
            float4 c = p;
            if (k + 1 < m) {
                int s2 = __shfl_sync(hmask, idx, k + 1, 16);
                const float4* nr = (s2 < N_CHR) ? (const float4*)(xchr + (size_t)s2 * 64)
                                                : (const float4*)(xslv + (size_t)(s2 - N_CHR) * 64);
                p = nr[l];
            }
            a.x += c.x; a.y += c.y; a.z += c.z; a.w += c.w;
        }
    }
    uint2 u; u.x = pack2(a.x, a.y); u.y = pack2(a.z, a.w);
    *(uint2*)(out + (size_t)node * 64 + l * 4) = u;
}

// 384-wide aggregation over fp16 rows -> relu -> fp16 output. 2 nodes/warp.
__global__ __launch_bounds__(256)
void gather384h_kernel(const __half* __restrict__ in, __half* __restrict__ out) {
    int lane = threadIdx.x & 31;
    int sub = lane >> 4;
    int l = lane & 15;
    unsigned hmask = 0xffffu << (sub * 16);
    int node = ((blockIdx.x * blockDim.x + threadIdx.x) >> 5) * 2 + sub;
    if (node >= NTOT) return;
    int start = g_off[node], deg = g_cursor[node] - start;
    float a[24];
    #pragma unroll
    for (int i = 0; i < 24; i++) a[i] = 0.f;
    for (int kb = 0; kb < deg; kb += 16) {
        int idx = (kb + l < deg) ? g_csr[start + kb + l] : 0;
        int m = min(16, deg - kb);
        int s = __shfl_sync(hmask, idx, 0, 16);
        const uint4* sr = (const uint4*)(in + (size_t)s * 384);
        uint4 p0 = sr[l], p1 = sr[l + 16], p2 = sr[l + 32];
        for (int k = 0; k < m; k++) {
            uint4 c0 = p0, c1 = p1, c2 = p2;
            if (k + 1 < m) {
                int s2 = __shfl_sync(hmask, idx, k + 1, 16);
                const uint4* nr = (const uint4*)(in + (size_t)s2 * 384);
                p0 = nr[l]; p1 = nr[l + 16]; p2 = nr[l + 32];
            }
            acc8(a, c0); acc8(a + 8, c1); acc8(a + 16, c2);
        }
    }
    uint4* orow = (uint4*)(out + (size_t)node * 384);
    uint4 o;
    o.x = pack2r(a[0], a[1]);   o.y = pack2r(a[2], a[3]);
    o.z = pack2r(a[4], a[5]);   o.w = pack2r(a[6], a[7]);
    orow[l] = o;
    o.x = pack2r(a[8], a[9]);   o.y = pack2r(a[10], a[11]);
    o.z = pack2r(a[12], a[13]); o.w = pack2r(a[14], a[15]);
    orow[l + 16] = o;
    o.x = pack2r(a[16], a[17]); o.y = pack2r(a[18], a[19]);
    o.z = pack2r(a[20], a[21]); o.w = pack2r(a[22], a[23]);
    orow[l + 32] = o;
}

// layer-2 aggregation (192-wide fp16 rows) + relu + global_add_pool. 2 nodes/warp.
__global__ __launch_bounds__(256)
void gather192h_pool_kernel(const __half* __restrict__ in,
                            const int* __restrict__ bchr, const int* __restrict__ bslv) {
    int lane = threadIdx.x & 31;
    int sub = lane >> 4;
    int l = lane & 15;
    unsigned hmask = 0xffffu << (sub * 16);
    int node = ((blockIdx.x * blockDim.x + threadIdx.x) >> 5) * 2 + sub;
    if (node >= NTOT) return;
    int start = g_off[node], deg = g_cursor[node] - start;
    float a[12];
    #pragma unroll
    for (int i = 0; i < 12; i++) a[i] = 0.f;
    for (int kb = 0; kb < deg; kb += 16) {
        int idx = (kb + l < deg) ? g_csr[start + kb + l] : 0;
        int m = min(16, deg - kb);
        int s = __shfl_sync(hmask, idx, 0, 16);
        const uint2* sr = (const uint2*)(in + (size_t)s * 192);
        uint2 p0 = sr[l], p1 = sr[l + 16], p2 = sr[l + 32];
        for (int k = 0; k < m; k++) {
            uint2 c0 = p0, c1 = p1, c2 = p2;
            if (k + 1 < m) {
                int s2 = __shfl_sync(hmask, idx, k + 1, 16);
                const uint2* nr = (const uint2*)(in + (size_t)s2 * 192);
                p0 = nr[l]; p1 = nr[l + 16]; p2 = nr[l + 32];
            }
            acc4(a, c0); acc4(a + 4, c1); acc4(a + 8, c2);
        }
    }
    #pragma unroll
    for (int i = 0; i < 12; i++) a[i] = fmaxf(a[i], 0.f);
    int b, colbase;
    if (node < N_CHR) { b = bchr[node]; colbase = 0; }
    else              { b = bslv[node - N_CHR]; colbase = 192; }
    float* prow = g_pool + (size_t)b * 384 + colbase;
    red_add_v4(prow + l * 4,       make_float4(a[0], a[1], a[2], a[3]));
    red_add_v4(prow + 64 + l * 4,  make_float4(a[4], a[5], a[6], a[7]));
    red_add_v4(prow + 128 + l * 4, make_float4(a[8], a[9], a[10], a[11]));
}

// ---------------- fused GEMM0+GEMM1: t1 = relu(aggx@W0) @ W1 --------------
// h0 tile lives only in smem. 256 threads, tile = 128 rows.
__global__ __launch_bounds__(256, 1)
void gemm01_kernel(const __half* __restrict__ in, __half* __restrict__ out,
                   const float* __restrict__ W0c, const float* __restrict__ W0s,
                   const float* __restrict__ W1c, const float* __restrict__ W1s) {
    constexpr int TR = 128;
    constexpr int LDA = 72;    // 64 + 8
    constexpr int LDW = 136;   // 128 + 8
    constexpr int ABUF = TR * LDA;

    extern __shared__ __half hsm[];
    __half* sA  = hsm;                         // [2][128][72]
    __half* sW0 = hsm + 2 * ABUF;              // [64][136]
    __half* sW1 = sW0 + 64 * LDW;              // [128][136]
    __half* sH  = sW1 + 128 * LDW;             // [128][136]

    const int e = blockIdx.y;
    const int branch = blockIdx.z;
    const int tid = threadIdx.x;
    const int wid = tid >> 5;
    const int lane = tid & 31;
    const int rowgrp = wid >> 1;   // 4 groups of 32 rows
    const int colgrp = wid & 1;    // 2 groups of 64 cols

    const int base  = branch ? N_CHR : 0;
    const int nrows = branch ? N_SLV : N_CHR;
    const int ntiles = (nrows + TR - 1) / TR;

    // weights fp32 -> fp16 smem [k][n]
    {
        const float* W0 = (branch ? W0s : W0c) + (size_t)e * 64 * 128;
        for (int idx = tid; idx < 64 * 128 / 4; idx += 256) {
            int k = idx / 32, c = idx % 32;
            float4 w = ((const float4*)W0)[idx];
            uint2 u; u.x = pack2(w.x, w.y); u.y = pack2(w.z, w.w);
            *(uint2*)(sW0 + k * LDW + c * 4) = u;
        }
        const float* W1 = (branch ? W1s : W1c) + (size_t)e * 128 * 128;
        for (int idx = tid; idx < 128 * 128 / 4; idx += 256) {
            int k = idx / 32, c = idx % 32;
            float4 w = ((const float4*)W1)[idx];
            uint2 u; u.x = pack2(w.x, w.y); u.y = pack2(w.z, w.w);
            *(uint2*)(sW1 + k * LDW + c * 4) = u;
        }
    }

    unsigned sa_base = (unsigned)__cvta_generic_to_shared(sA);
    unsigned sw0_base = (unsigned)__cvta_generic_to_shared(sW0);
    unsigned sw1_base = (unsigned)__cvta_generic_to_shared(sW1);
    unsigned sh_base = (unsigned)__cvta_generic_to_shared(sH);

    auto load_tile = [&](int t, int buf) {
        int row0 = base + t * TR;
        for (int i = tid; i < TR * 8; i += 256) {   // 8 uint4 per 64-wide row
            int r = i >> 3, c = i & 7;
            bool valid = (row0 + r) < base + nrows;
            int rr = valid ? (row0 + r) : 0;
            const void* g = in + (size_t)rr * 64 + c * 8;
            cp_async16z(sa_base + (unsigned)(buf * ABUF + r * LDA + c * 8) * 2, g, valid);
        }
    };

    int t0 = blockIdx.x;
    if (t0 < ntiles) load_tile(t0, 0);
    cp_commit();

    int bi = 0;
    for (int t = t0; t < ntiles; t += gridDim.x, bi ^= 1) {
        int tn = t + gridDim.x;
        if (tn < ntiles) load_tile(tn, bi ^ 1);
        cp_commit();
        cp_wait1();
        __syncthreads();

        int row0 = base + t * TR;
        int rcnt = min(TR, base + nrows - row0);
        unsigned abuf = sa_base + (unsigned)(bi * ABUF) * 2;
        int lrow = lane >> 2, lcol = (lane & 3) * 2;

        // ---- MMA1: h0 = relu(A @ W0) -> sH ----
        {
            float acc[2][8][4];
            #pragma unroll
            for (int mt = 0; mt < 2; mt++)
                #pragma unroll
                for (int nt = 0; nt < 8; nt++)
                    #pragma unroll
                    for (int q = 0; q < 4; q++) acc[mt][nt][q] = 0.f;
            #pragma unroll
            for (int ks = 0; ks < 4; ks++) {   // K = 64
                unsigned a[2][4];
                #pragma unroll
                for (int mt = 0; mt < 2; mt++) {
                    int r = rowgrp * 32 + mt * 16 + (lane & 15);
                    int c = ks * 16 + (lane >> 4) * 8;
                    ldsm_x4(a[mt], abuf + (unsigned)(r * LDA + c) * 2);
                }
                #pragma unroll
                for (int nt = 0; nt < 8; nt++) {
                    unsigned b[2];
                    int rk = ks * 16 + (lane & 15);
                    int cn = colgrp * 64 + nt * 8;
                    ldsm_x2t(b, sw0_base + (unsigned)(rk * LDW + cn) * 2);
                    #pragma unroll
                    for (int mt = 0; mt < 2; mt++)
                        mma16816(acc[mt][nt], a[mt], b);
                }
            }
            // epilogue 1: relu + fp16 into sH (unconditional; invalid rows are 0)
            #pragma unroll
            for (int mt = 0; mt < 2; mt++) {
                #pragma unroll
                for (int nt = 0; nt < 8; nt++) {
                    int col = colgrp * 64 + nt * 8 + lcol;
                    int r1 = rowgrp * 32 + mt * 16 + lrow;
                    *(__half2*)(sH + r1 * LDW + col) =
                        __floats2half2_rn(fmaxf(acc[mt][nt][0], 0.f), fmaxf(acc[mt][nt][1], 0.f));
                    *(__half2*)(sH + (r1 + 8) * LDW + col) =
                        __floats2half2_rn(fmaxf(acc[mt][nt][2], 0.f), fmaxf(acc[mt][nt][3], 0.f));
                }
            }
        }
        __syncthreads();

        // ---- MMA2: t1 = h0 @ W1 -> gmem ----
        {
            float acc[2][8][4];
            #pragma unroll
            for (int mt = 0; mt < 2; mt++)
                #pragma unroll
                for (int nt = 0; nt < 8; nt++)
                    #pragma unroll
                    for (int q = 0; q < 4; q++) acc[mt][nt][q] = 0.f;
            #pragma unroll
            for (int ks = 0; ks < 8; ks++) {   // K = 128
                unsigned a[2][4];
                #pragma unroll
                for (int mt = 0; mt < 2; mt++) {
                    int r = rowgrp * 32 + mt * 16 + (lane & 15);
                    int c = ks * 16 + (lane >> 4) * 8;
                    ldsm_x4(a[mt], sh_base + (unsigned)(r * LDW + c) * 2);
                }
                #pragma unroll
                for (int nt = 0; nt < 8; nt++) {
                    unsigned b[2];
                    int rk = ks * 16 + (lane & 15);
                    int cn = colgrp * 64 + nt * 8;
                    ldsm_x2t(b, sw1_base + (unsigned)(rk * LDW + cn) * 2);
                    #pragma unroll
                    for (int mt = 0; mt < 2; mt++)
                        mma16816(acc[mt][nt], a[mt], b);
                }
            }
            #pragma unroll
            for (int mt = 0; mt < 2; mt++) {
                #pragma unroll
                for (int nt = 0; nt < 8; nt++) {
                    int col = colgrp * 64 + nt * 8 + lcol;
                    int r1 = rowgrp * 32 + mt * 16 + lrow;
                    if (r1 < rcnt)
                        *(__half2*)(out + (size_t)(row0 + r1) * 384 + e * 128 + col) =
                            __floats2half2_rn(acc[mt][nt][0], acc[mt][nt][1]);
                    if (r1 + 8 < rcnt)
                        *(__half2*)(out + (size_t)(row0 + r1 + 8) * 384 + e * 128 + col) =
                            __floats2half2_rn(acc[mt][nt][2], acc[mt][nt][3]);
                }
            }
        }
        __syncthreads();
    }
}

// ---------------- fp16 tensor-core GEMM (cp.async double-buffered) --------
// (used for GEMM3: t2 = agg1 @ W2)
template<int K, int MOUT, bool RELU_OUT>
__global__ __launch_bounds__(256, 1)
void hgemm_kernel(const __half* __restrict__ in, __half* __restrict__ out,
                  const float* __restrict__ Wc, const float* __restrict__ Ws,
                  int in_stride, int in_eoff, int out_stride, int out_eoff) {
    constexpr int TR = 128;
    constexpr int CGS = MOUT / 64;
    constexpr int RGS = 8 / CGS;
    constexpr int WM = TR / RGS;
    constexpr int MT = WM / 16;
    constexpr int LDA = K + 8;
    constexpr int LDB = MOUT + 8;
    constexpr int KS = K / 16;
    constexpr int ABUF = TR * LDA;

    extern __shared__ __half hsm[];
    __half* sA = hsm;
    __half* sB = hsm + 2 * ABUF;

    const int e = blockIdx.y;
    const int branch = blockIdx.z;
    const int tid = threadIdx.x;
    const int wid = tid >> 5;
    const int lane = tid & 31;
    const int rowgrp = wid / CGS;
    const int colgrp = wid % CGS;

    const int base  = branch ? N_CHR : 0;
    const int nrows = branch ? N_SLV : N_CHR;
    const int ntiles = (nrows + TR - 1) / TR;
    const float* W = (branch ? Ws : Wc) + (size_t)e * K * MOUT;

    for (int idx = tid; idx < K * MOUT / 4; idx += 256) {
        int k = idx / (MOUT / 4), c = idx % (MOUT / 4);
        float4 w = ((const float4*)W)[idx];
        uint2 u; u.x = pack2(w.x, w.y); u.y = pack2(w.z, w.w);
        *(uint2*)(sB + k * LDB + c * 4) = u;
    }

    unsigned sa_base = (unsigned)__cvta_generic_to_shared(sA);
    unsigned sb_base = (unsigned)__cvta_generic_to_shared(sB);

    auto load_tile = [&](int t, int buf) {
        int row0 = base + t * TR;
        constexpr int C8 = TR * (K / 8);
        for (int i = tid; i < C8; i += 256) {
            int r = i / (K / 8), c = i % (K / 8);
            bool valid = (row0 + r) < base + nrows;
            int rr = valid ? (row0 + r) : base;
            const void* g = in + (size_t)rr * in_stride + (size_t)e * in_eoff + c * 8;
            cp_async16z(sa_base + (unsigned)(buf * ABUF + r * LDA + c * 8) * 2, g, valid);
        }
    };

    int t0 = blockIdx.x;
    if (t0 < ntiles) load_tile(t0, 0);
    cp_commit();

    int bi = 0;
    for (int t = t0; t < ntiles; t += gridDim.x, bi ^= 1) {
        int tn = t + gridDim.x;
        if (tn < ntiles) load_tile(tn, bi ^ 1);
        cp_commit();
        cp_wait1();
        __syncthreads();

        int row0 = base + t * TR;
        int rcnt = min(TR, base + nrows - row0);
        unsigned abuf = sa_base + (unsigned)(bi * ABUF) * 2;

        float acc[MT][8][4];
        #pragma unroll
        for (int mt = 0; mt < MT; mt++)
            #pragma unroll
            for (int nt = 0; nt < 8; nt++)
                #pragma unroll
                for (int q = 0; q < 4; q++) acc[mt][nt][q] = 0.f;

        #pragma unroll
        for (int ks = 0; ks < KS; ks++) {
            unsigned a[MT][4];
            #pragma unroll
            for (int mt = 0; mt < MT; mt++) {
                int r = rowgrp * WM + mt * 16 + (lane & 15);
                int c = ks * 16 + (lane >> 4) * 8;
                ldsm_x4(a[mt], abuf + (unsigned)(r * LDA + c) * 2);
            }
            #pragma unroll
            for (int nt = 0; nt < 8; nt++) {
                unsigned b[2];
                int rk = ks * 16 + (lane & 15);
                int cn = colgrp * 64 + nt * 8;
                ldsm_x2t(b, sb_base + (unsigned)(rk * LDB + cn) * 2);
                #pragma unroll
                for (int mt = 0; mt < MT; mt++)
                    mma16816(acc[mt][nt], a[mt], b);
            }
        }

        int lrow = lane >> 2, lcol = (lane & 3) * 2;
        #pragma unroll
        for (int mt = 0; mt < MT; mt++) {
            #pragma unroll
            for (int nt = 0; nt < 8; nt++) {
                int col = colgrp * 64 + nt * 8 + lcol;
                int r1 = rowgrp * WM + mt * 16 + lrow;
                float x0 = acc[mt][nt][0], x1 = acc[mt][nt][1];
                float x2 = acc[mt][nt][2], x3 = acc[mt][nt][3];
                if (RELU_OUT) {
                    x0 = fmaxf(x0, 0.f); x1 = fmaxf(x1, 0.f);
                    x2 = fmaxf(x2, 0.f); x3 = fmaxf(x3, 0.f);
                }
                if (r1 < rcnt) {
                    __half2 h = __floats2half2_rn(x0, x1);
                    *(__half2*)(out + (size_t)(row0 + r1) * out_stride + (size_t)e * out_eoff + col) = h;
                }
                if (r1 + 8 < rcnt) {
                    __half2 h = __floats2half2_rn(x2, x3);
                    *(__half2*)(out + (size_t)(row0 + r1 + 8) * out_stride + (size_t)e * out_eoff + col) = h;
                }
            }
        }
        __syncthreads();
    }
}

// ---------------- head: projection heads + concat + fc1 + fc2 -------------
__global__ __launch_bounds__(128)
void head_kernel(const float* __restrict__ cfcW, const float* __restrict__ cfcb,
                 const float* __restrict__ sfcW, const float* __restrict__ sfcb,
                 const float* __restrict__ fc1W, const float* __restrict__ fc1b,
                 const float* __restrict__ fc2W, const float* __restrict__ fc2b,
                 float* __restrict__ out) {
    __shared__ float sPool[384];
    __shared__ float sHg[768];
    __shared__ float sRed[128];
    const int b = blockIdx.x;
    const int tid = threadIdx.x;

    for (int i = tid; i < 384; i += 128) sPool[i] = g_pool[(size_t)b * 384 + i];
    __syncthreads();

    #pragma unroll
    for (int p = 0; p < 6; p++) {
        const bool slv = (p >= 3);
        const int e = slv ? (p - 3) : p;
        const float* W = slv ? sfcW : cfcW;
        const float* bias = slv ? sfcb : cfcb;
        const float* rep = sPool + (slv ? 192 : 0) + e * HALF;
        float acc = bias[e * DIM + tid];
        #pragma unroll 8
        for (int k = 0; k < HALF; k++)
            acc = fmaf(rep[k], W[(size_t)e * HALF * DIM + k * DIM + tid], acc);
        sHg[p * DIM + tid] = fmaxf(acc, 0.f);
    }
    __syncthreads();

    float acc = fc1b[tid];
    #pragma unroll 8
    for (int h = 0; h < 768; h++)
        acc = fmaf(sHg[h], fc1W[(size_t)h * DIM + tid], acc);
    float o1 = fmaxf(acc, 0.f);

    sRed[tid] = o1 * fc2W[tid];
    __syncthreads();
    if (tid < 64) sRed[tid] += sRed[tid + 64];
    __syncthreads();
    if (tid < 32) {
        float x = sRed[tid] + sRed[tid + 32];
        #pragma unroll
        for (int o = 16; o; o >>= 1) x += __shfl_down_sync(0xffffffffu, x, o);
        if (tid == 0) out[b] = x + fc2b[0];
    }
}

// ---------------- launch ----------------
extern "C" void kernel_launch(void* const* d_in, const int* in_sizes, int n_in,
                              void* d_out, int out_size) {
    const float* chr_x  = (const float*)d_in[0];
    const float* slv_x  = (const float*)d_in[1];
    const int*   chr_ei = (const int*)d_in[2];
    const int*   slv_ei = (const int*)d_in[3];
    const int*   chr_b  = (const int*)d_in[4];
    const int*   slv_b  = (const int*)d_in[5];
    const float* chr_W0 = (const float*)d_in[6];
    const float* chr_W1 = (const float*)d_in[7];
    const float* chr_W2 = (const float*)d_in[8];
    const float* slv_W0 = (const float*)d_in[9];
    const float* slv_W1 = (const float*)d_in[10];
    const float* slv_W2 = (const float*)d_in[11];
    const float* cfcW   = (const float*)d_in[12];
    const float* cfcb   = (const float*)d_in[13];
    const float* sfcW   = (const float*)d_in[14];
    const float* sfcb   = (const float*)d_in[15];
    const float* fc1W   = (const float*)d_in[16];
    const float* fc1b   = (const float*)d_in[17];
    const float* fc2W   = (const float*)d_in[18];
    const float* fc2b   = (const float*)d_in[19];
    float* out = (float*)d_out;

    __half *aggx, *buf1, *buf2;
    int* csr;
    cudaGetSymbolAddress((void**)&aggx, g_aggx);
    cudaGetSymbolAddress((void**)&buf1, g_buf1);
    cudaGetSymbolAddress((void**)&buf2, g_buf2);
    cudaGetSymbolAddress((void**)&csr, g_csr);

    // smem sizes
    constexpr int SM01 = (2 * 128 * 72 + 64 * 136 + 128 * 136 + 128 * 136) * 2;  // 123904
    constexpr int SM2  = (2 * 128 * 136 + 128 * 72) * 2;                          // 88064
    cudaFuncSetAttribute((const void*)gemm01_kernel,
                         cudaFuncAttributeMaxDynamicSharedMemorySize, SM01);
    cudaFuncSetAttribute((const void*)hgemm_kernel<128, 64, false>,
                         cudaFuncAttributeMaxDynamicSharedMemorySize, SM2);

    dim3 ggrid(50, ENS, 2);

    // ---- CSR build (g_deg zero at entry; re-zeroed inside gather64) ----
    count_deg_kernel<<<(ETOT + 255) / 256, 256>>>(chr_ei, slv_ei);   // + pool zero
    scan1_kernel<<<NB_SCAN, SCAN_BLK>>>(csr + ETOT - 128);  // raw block sums in csr tail
    scan23_kernel<<<(NTOT + 255) / 256, 256>>>(csr + ETOT - 128);
    fill_csr_kernel<<<(ETOT + 255) / 256, 256>>>(chr_ei, slv_ei);

    // ---- forward pass ----
    // 1) aggx = A x -> fp16 [N,64]
    gather64_kernel<<<(NTOT / 2 + 7) / 8, 256>>>(chr_x, slv_x, aggx);
    // 2+3) t1 = relu(aggx @ W0) @ W1 -> buf2 fp16 [N, 3*128] (h0 smem-only)
    gemm01_kernel<<<ggrid, 256, SM01>>>(aggx, buf2, chr_W0, slv_W0, chr_W1, slv_W1);
    // 4) agg1 = relu(A t1) -> buf1 fp16 [N, 3*128]
    gather384h_kernel<<<(NTOT / 2 + 7) / 8, 256>>>(buf2, buf1);
    // 5) t2 = agg1 @ W2 -> buf2 fp16 [N, 3*64]
    hgemm_kernel<128, 64, false><<<ggrid, 256, SM2>>>(
        buf1, buf2, chr_W2, slv_W2, ENS * DIM, DIM, ENS * HALF, HALF);
    // 6) pool[batch] += relu(A t2)
    gather192h_pool_kernel<<<(NTOT / 2 + 7) / 8, 256>>>(buf2, chr_b, slv_b);
    // 7) head
    head_kernel<<<B, 128>>>(cfcW, cfcb, sfcW, sfcb, fc1W, fc1b, fc2W, fc2b, out);
}

// round 15
// speedup vs baseline: 1.4851x; 1.0060x over previous
#include <cuda_runtime.h>
#include <cuda_bf16.h>
#include <cuda_fp16.h>

// ---------------- problem constants ----------------
constexpr int N_CHR = 50000, E_CHR = 500000;
constexpr int N_SLV = 30000, E_SLV = 300000;
constexpr int NTOT = N_CHR + N_SLV;      // 80000
constexpr int ETOT = E_CHR + E_SLV;      // 800000
constexpr int B    = 256;
constexpr int FEAT = 64;
constexpr int DIM  = 128;
constexpr int HALF = 64;
constexpr int ENS  = 3;
constexpr int SCAN_BLK = 1024;
constexpr int NB_SCAN = (NTOT + SCAN_BLK - 1) / SCAN_BLK;  // 79

// ---------------- scratch (device globals; no allocations allowed) --------
__device__ __align__(128) __half g_aggx[(size_t)NTOT * FEAT];
__device__ __align__(128) __half g_buf1[(size_t)NTOT * ENS * DIM];   // agg1 / t2
__device__ __align__(128) __half g_buf2[(size_t)NTOT * ENS * DIM];   // t1
__device__ float g_pool[(size_t)B * 2 * ENS * HALF];
__device__ int   g_deg[NTOT];        // ZERO at entry of every run (static init + re-zero in gather64)
__device__ int   g_incl[NTOT];
__device__ int   g_off[NTOT];
__device__ int   g_end[NTOT];        // end offset of each node (off + deg)
__device__ int   g_csr[ETOT];
__device__ int   g_rank[ETOT];       // per-edge rank within its dst bucket
__device__ int   g_bsum_raw[128];    // dedicated scan block-sum scratch (NO aliasing)

// ---------------- helpers ----------------
__device__ __forceinline__ void red_add_v4(float* p, float4 v) {
    asm volatile("red.global.add.v4.f32 [%0], {%1,%2,%3,%4};"
                 :: "l"(p), "f"(v.x), "f"(v.y), "f"(v.z), "f"(v.w)
                 : "memory");
}

__device__ __forceinline__ void edge_sd(int e, const int* __restrict__ ec,
                                        const int* __restrict__ es, int& src, int& dst) {
    if (e < E_CHR) { src = ec[e]; dst = ec[E_CHR + e]; }
    else { int e2 = e - E_CHR; src = N_CHR + es[e2]; dst = N_CHR + es[E_SLV + e2]; }
}

__device__ __forceinline__ void ldsm_x4(unsigned* r, unsigned addr) {
    asm volatile("ldmatrix.sync.aligned.m8n8.x4.shared.b16 {%0,%1,%2,%3}, [%4];"
                 : "=r"(r[0]), "=r"(r[1]), "=r"(r[2]), "=r"(r[3]) : "r"(addr));
}
__device__ __forceinline__ void ldsm_x2t(unsigned* r, unsigned addr) {
    asm volatile("ldmatrix.sync.aligned.m8n8.x2.trans.shared.b16 {%0,%1}, [%2];"
                 : "=r"(r[0]), "=r"(r[1]) : "r"(addr));
}
__device__ __forceinline__ void mma16816(float* d, const unsigned* a, const unsigned* b) {
    asm volatile("mma.sync.aligned.m16n8k16.row.col.f32.f16.f16.f32 "
                 "{%0,%1,%2,%3}, {%4,%5,%6,%7}, {%8,%9}, {%0,%1,%2,%3};"
                 : "+f"(d[0]), "+f"(d[1]), "+f"(d[2]), "+f"(d[3])
                 : "r"(a[0]), "r"(a[1]), "r"(a[2]), "r"(a[3]), "r"(b[0]), "r"(b[1]));
}
__device__ __forceinline__ void cp_async16z(unsigned sa, const void* g, bool v) {
    int sz = v ? 16 : 0;
    asm volatile("cp.async.cg.shared.global [%0], [%1], 16, %2;"
                 :: "r"(sa), "l"(g), "r"(sz) : "memory");
}
__device__ __forceinline__ void cp_commit() {
    asm volatile("cp.async.commit_group;" ::: "memory");
}
__device__ __forceinline__ void cp_wait1() {
    asm volatile("cp.async.wait_group 1;" ::: "memory");
}
__device__ __forceinline__ unsigned pack2(float x, float y) {
    __half2 h = __floats2half2_rn(x, y);
    return *(unsigned*)&h;
}
__device__ __forceinline__ unsigned pack2r(float x, float y) {
    return pack2(fmaxf(x, 0.f), fmaxf(y, 0.f));
}
__device__ __forceinline__ void acc4(float* a, uint2 v) {
    float2 f0 = __half22float2(*(__half2*)&v.x);
    float2 f1 = __half22float2(*(__half2*)&v.y);
    a[0] += f0.x; a[1] += f0.y; a[2] += f1.x; a[3] += f1.y;
}
__device__ __forceinline__ void acc8(float* a, uint4 v) {
    acc4(a, make_uint2(v.x, v.y));
    acc4(a + 4, make_uint2(v.z, v.w));
}

// ---------------- CSR build ----------------
// reads only dst; stores per-edge rank; also zeroes g_pool.
// requires g_deg == 0 at entry (maintained by gather64).
__global__ void count_deg_kernel(const int* __restrict__ ec, const int* __restrict__ es) {
    int e = blockIdx.x * blockDim.x + threadIdx.x;
    if (e < B * 384 / 4) ((float4*)g_pool)[e] = make_float4(0.f, 0.f, 0.f, 0.f);
    if (e >= ETOT) return;
    int dst = (e < E_CHR) ? ec[E_CHR + e] : N_CHR + es[E_SLV + (e - E_CHR)];
    g_rank[e] = atomicAdd(&g_deg[dst], 1);
}

// warp-shuffle inclusive scan per 1024-block; writes block sums.
__global__ __launch_bounds__(SCAN_BLK)
void scan1_kernel(int* __restrict__ bsum_raw) {
    __shared__ int warpsum[32];
    int tid = threadIdx.x, lane = tid & 31, wid = tid >> 5;
    int i = blockIdx.x * SCAN_BLK + tid;
    int v = (i < NTOT) ? g_deg[i] : 0;
    int x = v;
    #pragma unroll
    for (int o = 1; o < 32; o <<= 1) {
        int t = __shfl_up_sync(0xffffffffu, x, o);
        if (lane >= o) x += t;
    }
    if (lane == 31) warpsum[wid] = x;
    __syncthreads();
    if (wid == 0) {
        int y = warpsum[lane];
        #pragma unroll
        for (int o = 1; o < 32; o <<= 1) {
            int t = __shfl_up_sync(0xffffffffu, y, o);
            if (lane >= o) y += t;
        }
        warpsum[lane] = y;
    }
    __syncthreads();
    int incl = x + (wid ? warpsum[wid - 1] : 0);
    if (i < NTOT) g_incl[i] = incl;
    if (tid == SCAN_BLK - 1) bsum_raw[blockIdx.x] = incl;
}

// merged scan2+scan3: each block scans the 79 block sums, then writes offsets
__global__ void scan23_kernel(const int* __restrict__ bsum_raw) {
    __shared__ int s[128];
    __shared__ int r[128];
    int tid = threadIdx.x;
    if (tid < 128) {
        int v = (tid < NB_SCAN) ? bsum_raw[tid] : 0;
        s[tid] = v; r[tid] = v;
    }
    __syncthreads();
    #pragma unroll
    for (int off = 1; off < 128; off <<= 1) {
        int t = (tid < 128 && tid >= off) ? s[tid - off] : 0;
        __syncthreads();
        if (tid < 128) s[tid] += t;
        __syncthreads();
    }
    int i = blockIdx.x * blockDim.x + tid;
    if (i < NTOT) {
        int b = i >> 10;
        int incl = g_incl[i] + (s[b] - r[b]);
        g_off[i] = incl - g_deg[i];
        g_end[i] = incl;
    }
}

// atomic-free fill via precomputed ranks
__global__ void fill_csr_kernel(const int* __restrict__ ec, const int* __restrict__ es) {
    int e = blockIdx.x * blockDim.x + threadIdx.x;
    if (e >= ETOT) return;
    int src, dst; edge_sd(e, ec, es, src, dst);
    g_csr[g_off[dst] + g_rank[e]] = src;
}

// ---------------- gathers (2 nodes/warp, 1-ahead prefetch) ----------------
// first aggregation over raw fp32 features -> fp16 output; also re-zeroes g_deg.
__global__ __launch_bounds__(256)
void gather64_kernel(const float* __restrict__ xchr, const float* __restrict__ xslv,
                     __half* __restrict__ out) {
    int lane = threadIdx.x & 31;
    int sub = lane >> 4;
    int l = lane & 15;
    unsigned hmask = 0xffffu << (sub * 16);
    int node = ((blockIdx.x * blockDim.x + threadIdx.x) >> 5) * 2 + sub;
    if (node >= NTOT) return;
    int start = g_off[node], deg = g_end[node] - start;
    if (l == 0) g_deg[node] = 0;
    float4 a = make_float4(0.f, 0.f, 0.f, 0.f);
    for (int kb = 0; kb < deg; kb += 16) {
        int idx = (kb + l < deg) ? g_csr[start + kb + l] : 0;
        int m = min(16, deg - kb);
        int s = __shfl_sync(hmask, idx, 0, 16);
        const float4* sr = (s < N_CHR) ? (const float4*)(xchr + (size_t)s * 64)
                                       : (const float4*)(xslv + (size_t)(s - N_CHR) * 64);
        float4 p = sr[l];
        for (int k = 0; k < m; k++) {
            float4 c = p;
            if (k + 1 < m) {
                int s2 = __shfl_sync(hmask, idx, k + 1, 16);
                const float4* nr = (s2 < N_CHR) ? (const float4*)(xchr + (size_t)s2 * 64)
                                                : (const float4*)(xslv + (size_t)(s2 - N_CHR) * 64);
                p = nr[l];
            }
            a.x += c.x; a.y += c.y; a.z += c.z; a.w += c.w;
        }
    }
    uint2 u; u.x = pack2(a.x, a.y); u.y = pack2(a.z, a.w);
    *(uint2*)(out + (size_t)node * 64 + l * 4) = u;
}

// 384-wide aggregation over fp16 rows -> relu -> fp16 output. 2 nodes/warp.
__global__ __launch_bounds__(256)
void gather384h_kernel(const __half* __restrict__ in, __half* __restrict__ out) {
    int lane = threadIdx.x & 31;
    int sub = lane >> 4;
    int l = lane & 15;
    unsigned hmask = 0xffffu << (sub * 16);
    int node = ((blockIdx.x * blockDim.x + threadIdx.x) >> 5) * 2 + sub;
    if (node >= NTOT) return;
    int start = g_off[node], deg = g_end[node] - start;
    float a[24];
    #pragma unroll
    for (int i = 0; i < 24; i++) a[i] = 0.f;
    for (int kb = 0; kb < deg; kb += 16) {
        int idx = (kb + l < deg) ? g_csr[start + kb + l] : 0;
        int m = min(16, deg - kb);
        int s = __shfl_sync(hmask, idx, 0, 16);
        const uint4* sr = (const uint4*)(in + (size_t)s * 384);
        uint4 p0 = sr[l], p1 = sr[l + 16], p2 = sr[l + 32];
        for (int k = 0; k < m; k++) {
            uint4 c0 = p0, c1 = p1, c2 = p2;
            if (k + 1 < m) {
                int s2 = __shfl_sync(hmask, idx, k + 1, 16);
                const uint4* nr = (const uint4*)(in + (size_t)s2 * 384);
                p0 = nr[l]; p1 = nr[l + 16]; p2 = nr[l + 32];
            }
            acc8(a, c0); acc8(a + 8, c1); acc8(a + 16, c2);
        }
    }
    uint4* orow = (uint4*)(out + (size_t)node * 384);
    uint4 o;
    o.x = pack2r(a[0], a[1]);   o.y = pack2r(a[2], a[3]);
    o.z = pack2r(a[4], a[5]);   o.w = pack2r(a[6], a[7]);
    orow[l] = o;
    o.x = pack2r(a[8], a[9]);   o.y = pack2r(a[10], a[11]);
    o.z = pack2r(a[12], a[13]); o.w = pack2r(a[14], a[15]);
    orow[l + 16] = o;
    o.x = pack2r(a[16], a[17]); o.y = pack2r(a[18], a[19]);
    o.z = pack2r(a[20], a[21]); o.w = pack2r(a[22], a[23]);
    orow[l + 32] = o;
}

// layer-2 aggregation (192-wide fp16 rows) + relu + global_add_pool. 2 nodes/warp.
__global__ __launch_bounds__(256)
void gather192h_pool_kernel(const __half* __restrict__ in,
                            const int* __restrict__ bchr, const int* __restrict__ bslv) {
    int lane = threadIdx.x & 31;
    int sub = lane >> 4;
    int l = lane & 15;
    unsigned hmask = 0xffffu << (sub * 16);
    int node = ((blockIdx.x * blockDim.x + threadIdx.x) >> 5) * 2 + sub;
    if (node >= NTOT) return;
    int start = g_off[node], deg = g_end[node] - start;
    float a[12];
    #pragma unroll
    for (int i = 0; i < 12; i++) a[i] = 0.f;
    for (int kb = 0; kb < deg; kb += 16) {
        int idx = (kb + l < deg) ? g_csr[start + kb + l] : 0;
        int m = min(16, deg - kb);
        int s = __shfl_sync(hmask, idx, 0, 16);
        const uint2* sr = (const uint2*)(in + (size_t)s * 192);
        uint2 p0 = sr[l], p1 = sr[l + 16], p2 = sr[l + 32];
        for (int k = 0; k < m; k++) {
            uint2 c0 = p0, c1 = p1, c2 = p2;
            if (k + 1 < m) {
                int s2 = __shfl_sync(hmask, idx, k + 1, 16);
                const uint2* nr = (const uint2*)(in + (size_t)s2 * 192);
                p0 = nr[l]; p1 = nr[l + 16]; p2 = nr[l + 32];
            }
            acc4(a, c0); acc4(a + 4, c1); acc4(a + 8, c2);
        }
    }
    #pragma unroll
    for (int i = 0; i < 12; i++) a[i] = fmaxf(a[i], 0.f);
    int b, colbase;
    if (node < N_CHR) { b = bchr[node]; colbase = 0; }
    else              { b = bslv[node - N_CHR]; colbase = 192; }
    float* prow = g_pool + (size_t)b * 384 + colbase;
    red_add_v4(prow + l * 4,       make_float4(a[0], a[1], a[2], a[3]));
    red_add_v4(prow + 64 + l * 4,  make_float4(a[4], a[5], a[6], a[7]));
    red_add_v4(prow + 128 + l * 4, make_float4(a[8], a[9], a[10], a[11]));
}

// ---------------- fused GEMM0+GEMM1: t1 = relu(aggx@W0) @ W1 --------------
// h0 tile lives only in smem. 256 threads, tile = 128 rows.
__global__ __launch_bounds__(256, 1)
void gemm01_kernel(const __half* __restrict__ in, __half* __restrict__ out,
                   const float* __restrict__ W0c, const float* __restrict__ W0s,
                   const float* __restrict__ W1c, const float* __restrict__ W1s) {
    constexpr int TR = 128;
    constexpr int LDA = 72;    // 64 + 8
    constexpr int LDW = 136;   // 128 + 8
    constexpr int ABUF = TR * LDA;

    extern __shared__ __half hsm[];
    __half* sA  = hsm;                         // [2][128][72]
    __half* sW0 = hsm + 2 * ABUF;              // [64][136]
    __half* sW1 = sW0 + 64 * LDW;              // [128][136]
    __half* sH  = sW1 + 128 * LDW;             // [128][136]

    const int e = blockIdx.y;
    const int branch = blockIdx.z;
    const int tid = threadIdx.x;
    const int wid = tid >> 5;
    const int lane = tid & 31;
    const int rowgrp = wid >> 1;   // 4 groups of 32 rows
    const int colgrp = wid & 1;    // 2 groups of 64 cols

    const int base  = branch ? N_CHR : 0;
    const int nrows = branch ? N_SLV : N_CHR;
    const int ntiles = (nrows + TR - 1) / TR;

    // weights fp32 -> fp16 smem [k][n]
    {
        const float* W0 = (branch ? W0s : W0c) + (size_t)e * 64 * 128;
        for (int idx = tid; idx < 64 * 128 / 4; idx += 256) {
            int k = idx / 32, c = idx % 32;
            float4 w = ((const float4*)W0)[idx];
            uint2 u; u.x = pack2(w.x, w.y); u.y = pack2(w.z, w.w);
            *(uint2*)(sW0 + k * LDW + c * 4) = u;
        }
        const float* W1 = (branch ? W1s : W1c) + (size_t)e * 128 * 128;
        for (int idx = tid; idx < 128 * 128 / 4; idx += 256) {
            int k = idx / 32, c = idx % 32;
            float4 w = ((const float4*)W1)[idx];
            uint2 u; u.x = pack2(w.x, w.y); u.y = pack2(w.z, w.w);
            *(uint2*)(sW1 + k * LDW + c * 4) = u;
        }
    }

    unsigned sa_base = (unsigned)__cvta_generic_to_shared(sA);
    unsigned sw0_base = (unsigned)__cvta_generic_to_shared(sW0);
    unsigned sw1_base = (unsigned)__cvta_generic_to_shared(sW1);
    unsigned sh_base = (unsigned)__cvta_generic_to_shared(sH);

    auto load_tile = [&](int t, int buf) {
        int row0 = base + t * TR;
        for (int i = tid; i < TR * 8; i += 256) {   // 8 uint4 per 64-wide row
            int r = i >> 3, c = i & 7;
            bool valid = (row0 + r) < base + nrows;
            int rr = valid ? (row0 + r) : 0;
            const void* g = in + (size_t)rr * 64 + c * 8;
            cp_async16z(sa_base + (unsigned)(buf * ABUF + r * LDA + c * 8) * 2, g, valid);
        }
    };

    int t0 = blockIdx.x;
    if (t0 < ntiles) load_tile(t0, 0);
    cp_commit();

    int bi = 0;
    for (int t = t0; t < ntiles; t += gridDim.x, bi ^= 1) {
        int tn = t + gridDim.x;
        if (tn < ntiles) load_tile(tn, bi ^ 1);
        cp_commit();
        cp_wait1();
        __syncthreads();

        int row0 = base + t * TR;
        int rcnt = min(TR, base + nrows - row0);
        unsigned abuf = sa_base + (unsigned)(bi * ABUF) * 2;
        int lrow = lane >> 2, lcol = (lane & 3) * 2;

        // ---- MMA1: h0 = relu(A @ W0) -> sH ----
        {
            float acc[2][8][4];
            #pragma unroll
            for (int mt = 0; mt < 2; mt++)
                #pragma unroll
                for (int nt = 0; nt < 8; nt++)
                    #pragma unroll
                    for (int q = 0; q < 4; q++) acc[mt][nt][q] = 0.f;
            #pragma unroll
            for (int ks = 0; ks < 4; ks++) {   // K = 64
                unsigned a[2][4];
                #pragma unroll
                for (int mt = 0; mt < 2; mt++) {
                    int r = rowgrp * 32 + mt * 16 + (lane & 15);
                    int c = ks * 16 + (lane >> 4) * 8;
                    ldsm_x4(a[mt], abuf + (unsigned)(r * LDA + c) * 2);
                }
                #pragma unroll
                for (int nt = 0; nt < 8; nt++) {
                    unsigned b[2];
                    int rk = ks * 16 + (lane & 15);
                    int cn = colgrp * 64 + nt * 8;
                    ldsm_x2t(b, sw0_base + (unsigned)(rk * LDW + cn) * 2);
                    #pragma unroll
                    for (int mt = 0; mt < 2; mt++)
                        mma16816(acc[mt][nt], a[mt], b);
                }
            }
            // epilogue 1: relu + fp16 into sH (unconditional; invalid rows are 0)
            #pragma unroll
            for (int mt = 0; mt < 2; mt++) {
                #pragma unroll
                for (int nt = 0; nt < 8; nt++) {
                    int col = colgrp * 64 + nt * 8 + lcol;
                    int r1 = rowgrp * 32 + mt * 16 + lrow;
                    *(__half2*)(sH + r1 * LDW + col) =
                        __floats2half2_rn(fmaxf(acc[mt][nt][0], 0.f), fmaxf(acc[mt][nt][1], 0.f));
                    *(__half2*)(sH + (r1 + 8) * LDW + col) =
                        __floats2half2_rn(fmaxf(acc[mt][nt][2], 0.f), fmaxf(acc[mt][nt][3], 0.f));
                }
            }
        }
        __syncthreads();

        // ---- MMA2: t1 = h0 @ W1 -> gmem ----
        {
            float acc[2][8][4];
            #pragma unroll
            for (int mt = 0; mt < 2; mt++)
                #pragma unroll
                for (int nt = 0; nt < 8; nt++)
                    #pragma unroll
                    for (int q = 0; q < 4; q++) acc[mt][nt][q] = 0.f;
            #pragma unroll
            for (int ks = 0; ks < 8; ks++) {   // K = 128
                unsigned a[2][4];
                #pragma unroll
                for (int mt = 0; mt < 2; mt++) {
                    int r = rowgrp * 32 + mt * 16 + (lane & 15);
                    int c = ks * 16 + (lane >> 4) * 8;
                    ldsm_x4(a[mt], sh_base + (unsigned)(r * LDW + c) * 2);
                }
                #pragma unroll
                for (int nt = 0; nt < 8; nt++) {
                    unsigned b[2];
                    int rk = ks * 16 + (lane & 15);
                    int cn = colgrp * 64 + nt * 8;
                    ldsm_x2t(b, sw1_base + (unsigned)(rk * LDW + cn) * 2);
                    #pragma unroll
                    for (int mt = 0; mt < 2; mt++)
                        mma16816(acc[mt][nt], a[mt], b);
                }
            }
            #pragma unroll
            for (int mt = 0; mt < 2; mt++) {
                #pragma unroll
                for (int nt = 0; nt < 8; nt++) {
                    int col = colgrp * 64 + nt * 8 + lcol;
                    int r1 = rowgrp * 32 + mt * 16 + lrow;
                    if (r1 < rcnt)
                        *(__half2*)(out + (size_t)(row0 + r1) * 384 + e * 128 + col) =
                            __floats2half2_rn(acc[mt][nt][0], acc[mt][nt][1]);
                    if (r1 + 8 < rcnt)
                        *(__half2*)(out + (size_t)(row0 + r1 + 8) * 384 + e * 128 + col) =
                            __floats2half2_rn(acc[mt][nt][2], acc[mt][nt][3]);
                }
            }
        }
        __syncthreads();
    }
}

// ---------------- fp16 tensor-core GEMM (cp.async double-buffered) --------
// (used for GEMM3: t2 = agg1 @ W2)
template<int K, int MOUT, bool RELU_OUT>
__global__ __launch_bounds__(256, 1)
void hgemm_kernel(const __half* __restrict__ in, __half* __restrict__ out,
                  const float* __restrict__ Wc, const float* __restrict__ Ws,
                  int in_stride, int in_eoff, int out_stride, int out_eoff) {
    constexpr int TR = 128;
    constexpr int CGS = MOUT / 64;
    constexpr int RGS = 8 / CGS;
    constexpr int WM = TR / RGS;
    constexpr int MT = WM / 16;
    constexpr int LDA = K + 8;
    constexpr int LDB = MOUT + 8;
    constexpr int KS = K / 16;
    constexpr int ABUF = TR * LDA;

    extern __shared__ __half hsm[];
    __half* sA = hsm;
    __half* sB = hsm + 2 * ABUF;

    const int e = blockIdx.y;
    const int branch = blockIdx.z;
    const int tid = threadIdx.x;
    const int wid = tid >> 5;
    const int lane = tid & 31;
    const int rowgrp = wid / CGS;
    const int colgrp = wid % CGS;

    const int base  = branch ? N_CHR : 0;
    const int nrows = branch ? N_SLV : N_CHR;
    const int ntiles = (nrows + TR - 1) / TR;
    const float* W = (branch ? Ws : Wc) + (size_t)e * K * MOUT;

    for (int idx = tid; idx < K * MOUT / 4; idx += 256) {
        int k = idx / (MOUT / 4), c = idx % (MOUT / 4);
        float4 w = ((const float4*)W)[idx];
        uint2 u; u.x = pack2(w.x, w.y); u.y = pack2(w.z, w.w);
        *(uint2*)(sB + k * LDB + c * 4) = u;
    }

    unsigned sa_base = (unsigned)__cvta_generic_to_shared(sA);
    unsigned sb_base = (unsigned)__cvta_generic_to_shared(sB);

    auto load_tile = [&](int t, int buf) {
        int row0 = base + t * TR;
        constexpr int C8 = TR * (K / 8);
        for (int i = tid; i < C8; i += 256) {
            int r = i / (K / 8), c = i % (K / 8);
            bool valid = (row0 + r) < base + nrows;
            int rr = valid ? (row0 + r) : base;
            const void* g = in + (size_t)rr * in_stride + (size_t)e * in_eoff + c * 8;
            cp_async16z(sa_base + (unsigned)(buf * ABUF + r * LDA + c * 8) * 2, g, valid);
        }
    };

    int t0 = blockIdx.x;
    if (t0 < ntiles) load_tile(t0, 0);
    cp_commit();

    int bi = 0;
    for (int t = t0; t < ntiles; t += gridDim.x, bi ^= 1) {
        int tn = t + gridDim.x;
        if (tn < ntiles) load_tile(tn, bi ^ 1);
        cp_commit();
        cp_wait1();
        __syncthreads();

        int row0 = base + t * TR;
        int rcnt = min(TR, base + nrows - row0);
        unsigned abuf = sa_base + (unsigned)(bi * ABUF) * 2;

        float acc[MT][8][4];
        #pragma unroll
        for (int mt = 0; mt < MT; mt++)
            #pragma unroll
            for (int nt = 0; nt < 8; nt++)
                #pragma unroll
                for (int q = 0; q < 4; q++) acc[mt][nt][q] = 0.f;

        #pragma unroll
        for (int ks = 0; ks < KS; ks++) {
            unsigned a[MT][4];
            #pragma unroll
            for (int mt = 0; mt < MT; mt++) {
                int r = rowgrp * WM + mt * 16 + (lane & 15);
                int c = ks * 16 + (lane >> 4) * 8;
                ldsm_x4(a[mt], abuf + (unsigned)(r * LDA + c) * 2);
            }
            #pragma unroll
            for (int nt = 0; nt < 8; nt++) {
                unsigned b[2];
                int rk = ks * 16 + (lane & 15);
                int cn = colgrp * 64 + nt * 8;
                ldsm_x2t(b, sb_base + (unsigned)(rk * LDB + cn) * 2);
                #pragma unroll
                for (int mt = 0; mt < MT; mt++)
                    mma16816(acc[mt][nt], a[mt], b);
            }
        }

        int lrow = lane >> 2, lcol = (lane & 3) * 2;
        #pragma unroll
        for (int mt = 0; mt < MT; mt++) {
            #pragma unroll
            for (int nt = 0; nt < 8; nt++) {
                int col = colgrp * 64 + nt * 8 + lcol;
                int r1 = rowgrp * WM + mt * 16 + lrow;
                float x0 = acc[mt][nt][0], x1 = acc[mt][nt][1];
                float x2 = acc[mt][nt][2], x3 = acc[mt][nt][3];
                if (RELU_OUT) {
                    x0 = fmaxf(x0, 0.f); x1 = fmaxf(x1, 0.f);
                    x2 = fmaxf(x2, 0.f); x3 = fmaxf(x3, 0.f);
                }
                if (r1 < rcnt) {
                    __half2 h = __floats2half2_rn(x0, x1);
                    *(__half2*)(out + (size_t)(row0 + r1) * out_stride + (size_t)e * out_eoff + col) = h;
                }
                if (r1 + 8 < rcnt) {
                    __half2 h = __floats2half2_rn(x2, x3);
                    *(__half2*)(out + (size_t)(row0 + r1 + 8) * out_stride + (size_t)e * out_eoff + col) = h;
                }
            }
        }
        __syncthreads();
    }
}

// ---------------- head: projection heads + concat + fc1 + fc2 -------------
__global__ __launch_bounds__(128)
void head_kernel(const float* __restrict__ cfcW, const float* __restrict__ cfcb,
                 const float* __restrict__ sfcW, const float* __restrict__ sfcb,
                 const float* __restrict__ fc1W, const float* __restrict__ fc1b,
                 const float* __restrict__ fc2W, const float* __restrict__ fc2b,
                 float* __restrict__ out) {
    __shared__ float sPool[384];
    __shared__ float sHg[768];
    __shared__ float sRed[128];
    const int b = blockIdx.x;
    const int tid = threadIdx.x;

    for (int i = tid; i < 384; i += 128) sPool[i] = g_pool[(size_t)b * 384 + i];
    __syncthreads();

    #pragma unroll
    for (int p = 0; p < 6; p++) {
        const bool slv = (p >= 3);
        const int e = slv ? (p - 3) : p;
        const float* W = slv ? sfcW : cfcW;
        const float* bias = slv ? sfcb : cfcb;
        const float* rep = sPool + (slv ? 192 : 0) + e * HALF;
        float acc = bias[e * DIM + tid];
        #pragma unroll 8
        for (int k = 0; k < HALF; k++)
            acc = fmaf(rep[k], W[(size_t)e * HALF * DIM + k * DIM + tid], acc);
        sHg[p * DIM + tid] = fmaxf(acc, 0.f);
    }
    __syncthreads();

    float acc = fc1b[tid];
    #pragma unroll 8
    for (int h = 0; h < 768; h++)
        acc = fmaf(sHg[h], fc1W[(size_t)h * DIM + tid], acc);
    float o1 = fmaxf(acc, 0.f);

    sRed[tid] = o1 * fc2W[tid];
    __syncthreads();
    if (tid < 64) sRed[tid] += sRed[tid + 64];
    __syncthreads();
    if (tid < 32) {
        float x = sRed[tid] + sRed[tid + 32];
        #pragma unroll
        for (int o = 16; o; o >>= 1) x += __shfl_down_sync(0xffffffffu, x, o);
        if (tid == 0) out[b] = x + fc2b[0];
    }
}

// ---------------- launch ----------------
extern "C" void kernel_launch(void* const* d_in, const int* in_sizes, int n_in,
                              void* d_out, int out_size) {
    const float* chr_x  = (const float*)d_in[0];
    const float* slv_x  = (const float*)d_in[1];
    const int*   chr_ei = (const int*)d_in[2];
    const int*   slv_ei = (const int*)d_in[3];
    const int*   chr_b  = (const int*)d_in[4];
    const int*   slv_b  = (const int*)d_in[5];
    const float* chr_W0 = (const float*)d_in[6];
    const float* chr_W1 = (const float*)d_in[7];
    const float* chr_W2 = (const float*)d_in[8];
    const float* slv_W0 = (const float*)d_in[9];
    const float* slv_W1 = (const float*)d_in[10];
    const float* slv_W2 = (const float*)d_in[11];
    const float* cfcW   = (const float*)d_in[12];
    const float* cfcb   = (const float*)d_in[13];
    const float* sfcW   = (const float*)d_in[14];
    const float* sfcb   = (const float*)d_in[15];
    const float* fc1W   = (const float*)d_in[16];
    const float* fc1b   = (const float*)d_in[17];
    const float* fc2W   = (const float*)d_in[18];
    const float* fc2b   = (const float*)d_in[19];
    float* out = (float*)d_out;

    __half *aggx, *buf1, *buf2;
    int* bsum_raw;
    cudaGetSymbolAddress((void**)&aggx, g_aggx);
    cudaGetSymbolAddress((void**)&buf1, g_buf1);
    cudaGetSymbolAddress((void**)&buf2, g_buf2);
    cudaGetSymbolAddress((void**)&bsum_raw, g_bsum_raw);

    // smem sizes
    constexpr int SM01 = (2 * 128 * 72 + 64 * 136 + 128 * 136 + 128 * 136) * 2;  // 123904
    constexpr int SM2  = (2 * 128 * 136 + 128 * 72) * 2;                          // 88064
    cudaFuncSetAttribute((const void*)gemm01_kernel,
                         cudaFuncAttributeMaxDynamicSharedMemorySize, SM01);
    cudaFuncSetAttribute((const void*)hgemm_kernel<128, 64, false>,
                         cudaFuncAttributeMaxDynamicSharedMemorySize, SM2);

    dim3 ggrid(50, ENS, 2);

    // ---- CSR build (g_deg zero at entry; re-zeroed inside gather64) ----
    count_deg_kernel<<<(ETOT + 255) / 256, 256>>>(chr_ei, slv_ei);   // + pool zero + rank
    scan1_kernel<<<NB_SCAN, SCAN_BLK>>>(bsum_raw);                   // dedicated scratch
    scan23_kernel<<<(NTOT + 255) / 256, 256>>>(bsum_raw);
    fill_csr_kernel<<<(ETOT + 255) / 256, 256>>>(chr_ei, slv_ei);

    // ---- forward pass ----
    // 1) aggx = A x -> fp16 [N,64]
    gather64_kernel<<<(NTOT / 2 + 7) / 8, 256>>>(chr_x, slv_x, aggx);
    // 2+3) t1 = relu(aggx @ W0) @ W1 -> buf2 fp16 [N, 3*128] (h0 smem-only)
    gemm01_kernel<<<ggrid, 256, SM01>>>(aggx, buf2, chr_W0, slv_W0, chr_W1, slv_W1);
    // 4) agg1 = relu(A t1) -> buf1 fp16 [N, 3*128]
    gather384h_kernel<<<(NTOT / 2 + 7) / 8, 256>>>(buf2, buf1);
    // 5) t2 = agg1 @ W2 -> buf2 fp16 [N, 3*64]
    hgemm_kernel<128, 64, false><<<ggrid, 256, SM2>>>(
        buf1, buf2, chr_W2, slv_W2, ENS * DIM, DIM, ENS * HALF, HALF);
    // 6) pool[batch] += relu(A t2)
    gather192h_pool_kernel<<<(NTOT / 2 + 7) / 8, 256>>>(buf2, chr_b, slv_b);
    // 7) head
    head_kernel<<<B, 128>>>(cfcW, cfcb, sfcW, sfcb, fc1W, fc1b, fc2W, fc2b, out);
}